// round 14
// baseline (speedup 1.0000x reference)
#include <cuda_runtime.h>
#include <cuda_bf16.h>
#include <math.h>

#define B_    64
#define S_    256
#define BS    16384
#define M_    64
#define QD_   128
#define QAD_  256
#define VD_   128
#define FD_   128

typedef unsigned long long ull;

// ---------------- scratch ----------------
__device__ float g_w[BS * M_];
__device__ float g_e[BS * VD_];
__device__ float g_a[BS * VD_];
__device__ float g_reads[BS * VD_];
__device__ float g_partial[2 * 128];
__device__ float g_ewT[QAD_ * VD_];    // [256][128]
__device__ float g_awT[QAD_ * VD_];    // [256][128]
__device__ float g_rwT[256 * FD_];     // [256][128]
__device__ float g_keyT[QD_ * M_];     // [128][64]

// ---------------- helpers ----------------
__device__ __forceinline__ ull dup2(float x) {
    ull r; unsigned xi = __float_as_uint(x);
    asm("mov.b64 %0, {%1, %1};" : "=l"(r) : "r"(xi));
    return r;
}
__device__ __forceinline__ ull pack2(float lo, float hi) {
    ull r; unsigned a = __float_as_uint(lo), b = __float_as_uint(hi);
    asm("mov.b64 %0, {%1, %2};" : "=l"(r) : "r"(a), "r"(b));
    return r;
}
__device__ __forceinline__ void unpack2(ull v, float& lo, float& hi) {
    unsigned a, b;
    asm("mov.b64 {%0, %1}, %2;" : "=r"(a), "=r"(b) : "l"(v));
    lo = __uint_as_float(a); hi = __uint_as_float(b);
}
__device__ __forceinline__ void fma2(ull& d, ull a, ull b) {
    asm("fma.rn.f32x2 %0, %1, %2, %0;" : "+l"(d) : "l"(a), "l"(b));
}
__device__ __forceinline__ void cp16(unsigned s, const float* g) {
    asm volatile("cp.async.cg.shared.global [%0], [%1], 16;" :: "r"(s), "l"(g));
}
#define CP_COMMIT() asm volatile("cp.async.commit_group;")
#define CP_WAIT0()  asm volatile("cp.async.wait_group 0;" ::: "memory")

// ============================================================================
// K0: transpose weights into k-major scratch
// ============================================================================
__global__ void transpose_kernel(const float* __restrict__ ew,
                                 const float* __restrict__ aw,
                                 const float* __restrict__ rw,
                                 const float* __restrict__ key) {
    int t = blockIdx.x * 256 + threadIdx.x;
    int which = blockIdx.y;
    if (which < 3) {
        int k = t >> 7, n = t & 127;
        const float* src = which == 0 ? ew : (which == 1 ? aw : rw);
        float* dst = which == 0 ? g_ewT : (which == 1 ? g_awT : g_rwT);
        dst[k * 128 + n] = src[n * 256 + k];
    } else {
        if (t < QD_ * M_) {
            int k = t >> 6, n = t & 63;
            g_keyT[k * 64 + n] = key[n * 128 + k];
        }
    }
}

// ============================================================================
// K1: w = softmax(q_emb @ mem_key^T)
// ============================================================================
__global__ __launch_bounds__(256, 2) void w_kernel(const int* __restrict__ q_data,
                                                   const float* __restrict__ q_w) {
    __shared__ union {
        struct {
            __align__(16) float As[2][16][132];
            __align__(16) float Bs[2][16][68];
        } g;
        float logits[128][65];
    } sm;
    __shared__ int idx_sh[128];

    int tid = threadIdx.x;
    int r0  = blockIdx.x * 128;
    if (tid < 128) idx_sh[tid] = q_data[r0 + tid];
    __syncthreads();

    int tx = tid & 15, ty = tid >> 4;
    int rowL = tid >> 2;
    int kq   = (tid & 3) * 4;

    int bkk = tid >> 4, bcc = (tid & 15) * 4;
    unsigned bs_base = (unsigned)__cvta_generic_to_shared(&sm.g.Bs[0][0][0]);
    unsigned bs_off  = (unsigned)((bkk * 68 + bcc) * 4);
    const unsigned BS_BUF = 16 * 68 * 4;

    ull acc[8][2];
#pragma unroll
    for (int i = 0; i < 8; i++) { acc[i][0] = 0ull; acc[i][1] = 0ull; }

    float4 pa0, pa1;
    pa0 = *(const float4*)(q_w + (long)idx_sh[rowL] * QD_ + kq);
    pa1 = *(const float4*)(q_w + (long)idx_sh[rowL + 64] * QD_ + kq);
    cp16(bs_base + bs_off, g_keyT + bkk * 64 + bcc);
    CP_COMMIT();
    {
        float* a = &sm.g.As[0][kq][0];
        a[0*132+rowL]=pa0.x; a[1*132+rowL]=pa0.y; a[2*132+rowL]=pa0.z; a[3*132+rowL]=pa0.w;
        a[0*132+rowL+64]=pa1.x; a[1*132+rowL+64]=pa1.y; a[2*132+rowL+64]=pa1.z; a[3*132+rowL+64]=pa1.w;
    }
    CP_WAIT0();
    __syncthreads();

    for (int c = 0; c < 8; c++) {
        int cur = c & 1, nb = cur ^ 1;
        if (c + 1 < 8) {
            int k0 = (c + 1) * 16;
            pa0 = *(const float4*)(q_w + (long)idx_sh[rowL] * QD_ + k0 + kq);
            pa1 = *(const float4*)(q_w + (long)idx_sh[rowL + 64] * QD_ + k0 + kq);
            cp16(bs_base + nb * BS_BUF + bs_off, g_keyT + (k0 + bkk) * 64 + bcc);
            CP_COMMIT();
        }
#pragma unroll
        for (int kk = 0; kk < 16; kk++) {
            const float* ap = &sm.g.As[cur][kk][ty * 8];
            float4 a0 = *(const float4*)ap;
            float4 a1 = *(const float4*)(ap + 4);
            ulonglong2 bv = *(const ulonglong2*)&sm.g.Bs[cur][kk][tx * 4];
            ull ad[8] = {dup2(a0.x), dup2(a0.y), dup2(a0.z), dup2(a0.w),
                         dup2(a1.x), dup2(a1.y), dup2(a1.z), dup2(a1.w)};
#pragma unroll
            for (int i = 0; i < 8; i++) {
                fma2(acc[i][0], ad[i], bv.x);
                fma2(acc[i][1], ad[i], bv.y);
            }
        }
        if (c + 1 < 8) {
            float* a = &sm.g.As[nb][kq][0];
            a[0*132+rowL]=pa0.x; a[1*132+rowL]=pa0.y; a[2*132+rowL]=pa0.z; a[3*132+rowL]=pa0.w;
            a[0*132+rowL+64]=pa1.x; a[1*132+rowL+64]=pa1.y; a[2*132+rowL+64]=pa1.z; a[3*132+rowL+64]=pa1.w;
            CP_WAIT0();
        }
        __syncthreads();
    }

#pragma unroll
    for (int i = 0; i < 8; i++) {
        float v0, v1, v2, v3;
        unpack2(acc[i][0], v0, v1);
        unpack2(acc[i][1], v2, v3);
        float* lr = &sm.logits[ty * 8 + i][tx * 4];
        lr[0] = v0; lr[1] = v1; lr[2] = v2; lr[3] = v3;
    }
    __syncthreads();

    int wid = tid >> 5, lane = tid & 31;
    for (int rr = wid; rr < 128; rr += 8) {
        float v0 = sm.logits[rr][lane], v1 = sm.logits[rr][lane + 32];
        float mx = fmaxf(v0, v1);
#pragma unroll
        for (int o = 16; o; o >>= 1) mx = fmaxf(mx, __shfl_xor_sync(0xFFFFFFFFu, mx, o));
        float e0 = __expf(v0 - mx), e1 = __expf(v1 - mx);
        float s = e0 + e1;
#pragma unroll
        for (int o = 16; o; o >>= 1) s += __shfl_xor_sync(0xFFFFFFFFu, s, o);
        float inv = 1.f / s;
        g_w[(r0 + rr) * M_ + lane]      = e0 * inv;
        g_w[(r0 + rr) * M_ + 32 + lane] = e1 * inv;
    }
}

// ============================================================================
// K2: e/a GEMM
// ============================================================================
__global__ __launch_bounds__(256, 2) void ea_kernel(const int* __restrict__ qa_data,
                                                    const float* __restrict__ qa_w,
                                                    const float* __restrict__ eb,
                                                    const float* __restrict__ ab) {
    __shared__ __align__(16) float As[2][16][132];
    __shared__ __align__(16) float Bs[2][16][132];
    __shared__ int idx_sh[128];

    int tid = threadIdx.x;
    int r0  = blockIdx.x * 128;
    int half = blockIdx.y;
    const float* WT   = half ? g_awT : g_ewT;
    const float* bias = half ? ab : eb;
    if (tid < 128) idx_sh[tid] = qa_data[r0 + tid];
    __syncthreads();

    int tx = tid & 15, ty = tid >> 4;
    int rowL = tid >> 2;
    int kq   = (tid & 3) * 4;

    int ch0 = tid, ch1 = tid + 256;
    int bkk0 = ch0 >> 5, bcc0 = (ch0 & 31) * 4;
    int bkk1 = ch1 >> 5, bcc1 = (ch1 & 31) * 4;
    unsigned bs_base = (unsigned)__cvta_generic_to_shared(&Bs[0][0][0]);
    unsigned bo0 = (unsigned)((bkk0 * 132 + bcc0) * 4);
    unsigned bo1 = (unsigned)((bkk1 * 132 + bcc1) * 4);
    const unsigned BS_BUF = 16 * 132 * 4;

    ull acc[8][4];
#pragma unroll
    for (int i = 0; i < 8; i++)
#pragma unroll
        for (int j = 0; j < 4; j++) acc[i][j] = 0ull;

    float4 pa0, pa1;
    pa0 = *(const float4*)(qa_w + (long)idx_sh[rowL] * QAD_ + kq);
    pa1 = *(const float4*)(qa_w + (long)idx_sh[rowL + 64] * QAD_ + kq);
    cp16(bs_base + bo0, WT + bkk0 * 128 + bcc0);
    cp16(bs_base + bo1, WT + bkk1 * 128 + bcc1);
    CP_COMMIT();
    {
        float* a = &As[0][kq][0];
        a[0*132+rowL]=pa0.x; a[1*132+rowL]=pa0.y; a[2*132+rowL]=pa0.z; a[3*132+rowL]=pa0.w;
        a[0*132+rowL+64]=pa1.x; a[1*132+rowL+64]=pa1.y; a[2*132+rowL+64]=pa1.z; a[3*132+rowL+64]=pa1.w;
    }
    CP_WAIT0();
    __syncthreads();

    for (int c = 0; c < 16; c++) {
        int cur = c & 1, nb = cur ^ 1;
        if (c + 1 < 16) {
            int k0 = (c + 1) * 16;
            pa0 = *(const float4*)(qa_w + (long)idx_sh[rowL] * QAD_ + k0 + kq);
            pa1 = *(const float4*)(qa_w + (long)idx_sh[rowL + 64] * QAD_ + k0 + kq);
            cp16(bs_base + nb * BS_BUF + bo0, WT + (k0 + bkk0) * 128 + bcc0);
            cp16(bs_base + nb * BS_BUF + bo1, WT + (k0 + bkk1) * 128 + bcc1);
            CP_COMMIT();
        }
#pragma unroll
        for (int kk = 0; kk < 16; kk++) {
            const float* ap = &As[cur][kk][ty * 8];
            float4 a0 = *(const float4*)ap;
            float4 a1 = *(const float4*)(ap + 4);
            ulonglong2 b01 = *(const ulonglong2*)&Bs[cur][kk][tx * 8];
            ulonglong2 b23 = *(const ulonglong2*)(&Bs[cur][kk][tx * 8] + 4);
            ull ad[8] = {dup2(a0.x), dup2(a0.y), dup2(a0.z), dup2(a0.w),
                         dup2(a1.x), dup2(a1.y), dup2(a1.z), dup2(a1.w)};
#pragma unroll
            for (int i = 0; i < 8; i++) {
                fma2(acc[i][0], ad[i], b01.x);
                fma2(acc[i][1], ad[i], b01.y);
                fma2(acc[i][2], ad[i], b23.x);
                fma2(acc[i][3], ad[i], b23.y);
            }
        }
        if (c + 1 < 16) {
            float* a = &As[nb][kq][0];
            a[0*132+rowL]=pa0.x; a[1*132+rowL]=pa0.y; a[2*132+rowL]=pa0.z; a[3*132+rowL]=pa0.w;
            a[0*132+rowL+64]=pa1.x; a[1*132+rowL+64]=pa1.y; a[2*132+rowL+64]=pa1.z; a[3*132+rowL+64]=pa1.w;
            CP_WAIT0();
        }
        __syncthreads();
    }

    float* dst = half ? g_a : g_e;
#pragma unroll
    for (int i = 0; i < 8; i++) {
        int r = r0 + ty * 8 + i;
        float o[8];
        unpack2(acc[i][0], o[0], o[1]);
        unpack2(acc[i][1], o[2], o[3]);
        unpack2(acc[i][2], o[4], o[5]);
        unpack2(acc[i][3], o[6], o[7]);
        float res[8];
#pragma unroll
        for (int j = 0; j < 8; j++) {
            float x = o[j] + __ldg(bias + tx * 8 + j);
            res[j] = half ? tanhf(x) : (1.f / (1.f + __expf(-x)));
        }
        float4* dp = (float4*)(dst + (long)r * VD_ + tx * 8);
        dp[0] = make_float4(res[0], res[1], res[2], res[3]);
        dp[1] = make_float4(res[4], res[5], res[6], res[7]);
    }
}

// ============================================================================
// K3: sequential memory scan.  256 threads, grid = B_*8 (16 v-cols per block).
//   w read directly from global (L2-resident, LDG.128, distance-2 prefetch).
//   ea in smem (32KB).  Lane map: 16 mh x 2 vl; thread owns 4 m (2 f32x2).
// ============================================================================
__global__ __launch_bounds__(256) void scan_kernel(const float* __restrict__ mem_value0) {
    extern __shared__ float smd[];
    float* ea_all = smd;                   // [128][16][4]: (t/2)*64 + vloc*4 + (t&1)*2

    int bb = blockIdx.x >> 3, vh = blockIdx.x & 7;   // vh: 16-col slice
    int tid = threadIdx.x;
    int rbase = bb * S_;

    // preload e,a packed 2 steps per 16B (16 cols)
    for (int f = tid; f < S_ * 4; f += 256) {
        int t = f >> 2, c = (f & 3) * 4;
        float4 e4 = *(const float4*)(g_e + (long)(rbase + t) * VD_ + vh * 16 + c);
        float4 a4 = *(const float4*)(g_a + (long)(rbase + t) * VD_ + vh * 16 + c);
        float* base = &ea_all[(t >> 1) * 64 + (t & 1) * 2];
        *(float2*)&base[(c + 0) * 4] = make_float2(e4.x, a4.x);
        *(float2*)&base[(c + 1) * 4] = make_float2(e4.y, a4.y);
        *(float2*)&base[(c + 2) * 4] = make_float2(e4.z, a4.z);
        *(float2*)&base[(c + 3) * 4] = make_float2(e4.w, a4.w);
    }

    int lane = tid & 31, wid = tid >> 5;           // wid 0..7
    int mh = lane & 15, vl = lane >> 4;            // mh 0..15, vl 0..1
    int vloc = wid * 2 + vl;                       // 0..15
    int v = vh * 16 + vloc;
    int mb = mh * 4;                               // 4 m-values per thread

    const float* wsrc = g_w + (long)rbase * M_ + mb;   // stride 64 per step

    ull mm[2];
#pragma unroll
    for (int i = 0; i < 2; i++) {
        int m0 = mb + 2 * i;
        mm[i] = pack2(mem_value0[m0 * VD_ + v], mem_value0[(m0 + 1) * VD_ + v]);
    }
    bool b8 = (mh & 8) != 0, b4 = (mh & 4) != 0, b2 = (mh & 2) != 0, b1 = (mh & 1) != 0;

    // distance-2 w prefetch
    ulonglong2 wbuf[2];
    wbuf[0] = *(const ulonglong2*)(wsrc + 0 * 64);
    wbuf[1] = *(const ulonglong2*)(wsrc + 1 * 64);
    __syncthreads();

    for (int t0 = 0; t0 < S_; t0 += 16) {
        float p[16];
#pragma unroll
        for (int j = 0; j < 8; j++) {
            float4 eab = *(const float4*)&ea_all[((t0 >> 1) + j) * 64 + vloc * 4];
#pragma unroll
            for (int s = 0; s < 2; s++) {
                int u = 2 * j + s;
                int t = t0 + u;
                ulonglong2 wA = wbuf[u & 1];
                // prefetch t+2 (wraps harmlessly within array until last two steps)
                if (t + 2 < S_) wbuf[u & 1] = *(const ulonglong2*)(wsrc + (t + 2) * 64);
                float ec = s ? eab.z : eab.x;
                float ac = s ? eab.w : eab.y;
                ull ne2 = dup2(-ec);
                ull a2v = dup2(ac);
                ull rd2 = 0ull;
#pragma unroll
                for (int i = 0; i < 2; i++) {
                    ull w2 = (i == 0) ? wA.x : wA.y;
                    ull tt = a2v; fma2(tt, ne2, mm[i]);   // a - e*mem
                    fma2(rd2, w2, mm[i]);                 // read uses old mem
                    fma2(mm[i], w2, tt);                  // mem += w*(a - e*mem)
                }
                float rl, rh; unpack2(rd2, rl, rh);
                p[u] = rl + rh;
            }
        }

        // reduce-scatter across 16 mh-lanes: 15 shfls; thread ends owning step t0+mh.
        float q8[8];
#pragma unroll
        for (int x = 0; x < 8; x++) {
            float send = b8 ? p[x] : p[x + 8];
            float recv = __shfl_xor_sync(0xFFFFFFFFu, send, 8);
            q8[x] = (b8 ? p[x + 8] : p[x]) + recv;
        }
        float q4[4];
#pragma unroll
        for (int x = 0; x < 4; x++) {
            float send = b4 ? q8[x] : q8[x + 4];
            float recv = __shfl_xor_sync(0xFFFFFFFFu, send, 4);
            q4[x] = (b4 ? q8[x + 4] : q8[x]) + recv;
        }
        float q2[2];
#pragma unroll
        for (int x = 0; x < 2; x++) {
            float send = b2 ? q4[x] : q4[x + 2];
            float recv = __shfl_xor_sync(0xFFFFFFFFu, send, 2);
            q2[x] = (b2 ? q4[x + 2] : q4[x]) + recv;
        }
        {
            float send = b1 ? q2[0] : q2[1];
            float recv = __shfl_xor_sync(0xFFFFFFFFu, send, 1);
            float rd = (b1 ? q2[1] : q2[0]) + recv;
            g_reads[(long)(rbase + t0 + mh) * VD_ + v] = rd;
        }
    }
}

// ============================================================================
// K4: h = tanh([reads,q_emb] @ rwT + rb) fused with pred + BCE.
// ============================================================================
__global__ __launch_bounds__(256, 2) void read_pred_kernel(const int* __restrict__ q_data,
                                                           const float* __restrict__ q_w,
                                                           const float* __restrict__ rb,
                                                           const float* __restrict__ target,
                                                           const float* __restrict__ pw,
                                                           const float* __restrict__ pb,
                                                           float* __restrict__ out) {
    __shared__ __align__(16) float As[2][16][132];
    __shared__ __align__(16) float Bs[2][16][132];
    __shared__ int idx_sh[128];

    int tid = threadIdx.x;
    int r0  = blockIdx.x * 128;
    if (tid < 128) idx_sh[tid] = q_data[r0 + tid];
    __syncthreads();

    int tx = tid & 15, ty = tid >> 4;
    int rowL = tid >> 2;
    int kq   = (tid & 3) * 4;

    int ch0 = tid, ch1 = tid + 256;
    int bkk0 = ch0 >> 5, bcc0 = (ch0 & 31) * 4;
    int bkk1 = ch1 >> 5, bcc1 = (ch1 & 31) * 4;
    unsigned bs_base = (unsigned)__cvta_generic_to_shared(&Bs[0][0][0]);
    unsigned bo0 = (unsigned)((bkk0 * 132 + bcc0) * 4);
    unsigned bo1 = (unsigned)((bkk1 * 132 + bcc1) * 4);
    const unsigned BS_BUF = 16 * 132 * 4;

    ull acc[8][4];
#pragma unroll
    for (int i = 0; i < 8; i++)
#pragma unroll
        for (int j = 0; j < 4; j++) acc[i][j] = 0ull;

    float4 pa0, pa1;
    pa0 = *(const float4*)(g_reads + (long)(r0 + rowL) * VD_ + kq);
    pa1 = *(const float4*)(g_reads + (long)(r0 + rowL + 64) * VD_ + kq);
    cp16(bs_base + bo0, g_rwT + bkk0 * 128 + bcc0);
    cp16(bs_base + bo1, g_rwT + bkk1 * 128 + bcc1);
    CP_COMMIT();
    {
        float* a = &As[0][kq][0];
        a[0*132+rowL]=pa0.x; a[1*132+rowL]=pa0.y; a[2*132+rowL]=pa0.z; a[3*132+rowL]=pa0.w;
        a[0*132+rowL+64]=pa1.x; a[1*132+rowL+64]=pa1.y; a[2*132+rowL+64]=pa1.z; a[3*132+rowL+64]=pa1.w;
    }
    CP_WAIT0();
    __syncthreads();

    for (int c = 0; c < 16; c++) {
        int cur = c & 1, nb = cur ^ 1;
        if (c + 1 < 16) {
            int k0 = (c + 1) * 16;
            if (k0 < 128) {
                pa0 = *(const float4*)(g_reads + (long)(r0 + rowL) * VD_ + k0 + kq);
                pa1 = *(const float4*)(g_reads + (long)(r0 + rowL + 64) * VD_ + k0 + kq);
            } else {
                pa0 = *(const float4*)(q_w + (long)idx_sh[rowL] * QD_ + (k0 - 128) + kq);
                pa1 = *(const float4*)(q_w + (long)idx_sh[rowL + 64] * QD_ + (k0 - 128) + kq);
            }
            cp16(bs_base + nb * BS_BUF + bo0, g_rwT + (k0 + bkk0) * 128 + bcc0);
            cp16(bs_base + nb * BS_BUF + bo1, g_rwT + (k0 + bkk1) * 128 + bcc1);
            CP_COMMIT();
        }
#pragma unroll
        for (int kk = 0; kk < 16; kk++) {
            const float* ap = &As[cur][kk][ty * 8];
            float4 a0 = *(const float4*)ap;
            float4 a1 = *(const float4*)(ap + 4);
            ulonglong2 b01 = *(const ulonglong2*)&Bs[cur][kk][tx * 8];
            ulonglong2 b23 = *(const ulonglong2*)(&Bs[cur][kk][tx * 8] + 4);
            ull ad[8] = {dup2(a0.x), dup2(a0.y), dup2(a0.z), dup2(a0.w),
                         dup2(a1.x), dup2(a1.y), dup2(a1.z), dup2(a1.w)};
#pragma unroll
            for (int i = 0; i < 8; i++) {
                fma2(acc[i][0], ad[i], b01.x);
                fma2(acc[i][1], ad[i], b01.y);
                fma2(acc[i][2], ad[i], b23.x);
                fma2(acc[i][3], ad[i], b23.y);
            }
        }
        if (c + 1 < 16) {
            float* a = &As[nb][kq][0];
            a[0*132+rowL]=pa0.x; a[1*132+rowL]=pa0.y; a[2*132+rowL]=pa0.z; a[3*132+rowL]=pa0.w;
            a[0*132+rowL+64]=pa1.x; a[1*132+rowL+64]=pa1.y; a[2*132+rowL+64]=pa1.z; a[3*132+rowL+64]=pa1.w;
            CP_WAIT0();
        }
        __syncthreads();
    }

    float pbv = __ldg(pb);
    float s_bce = 0.f, s_m = 0.f;
#pragma unroll
    for (int i = 0; i < 8; i++) {
        int r = r0 + ty * 8 + i;
        float o[8];
        unpack2(acc[i][0], o[0], o[1]);
        unpack2(acc[i][1], o[2], o[3]);
        unpack2(acc[i][2], o[4], o[5]);
        unpack2(acc[i][3], o[6], o[7]);
        float part = 0.f;
#pragma unroll
        for (int j = 0; j < 8; j++) {
            int vv = tx * 8 + j;
            float hv = tanhf(o[j] + __ldg(rb + vv));
            part = fmaf(hv, __ldg(pw + vv), part);
        }
        part += __shfl_xor_sync(0xFFFFFFFFu, part, 1);
        part += __shfl_xor_sync(0xFFFFFFFFu, part, 2);
        part += __shfl_xor_sync(0xFFFFFFFFu, part, 4);
        part += __shfl_xor_sync(0xFFFFFFFFu, part, 8);
        if (tx == 0) {
            float logit = part + pbv;
            float pred = 1.f / (1.f + __expf(-logit));
            float tgt  = target[r];
            out[1 + r]      = pred;
            out[1 + BS + r] = tgt;
            float spa = log1pf(__expf(-fabsf(logit)));
            float sp_n = fmaxf(-logit, 0.f) + spa;
            float sp_p = fmaxf(logit, 0.f) + spa;
            float msk = (tgt >= 0.f) ? 1.f : 0.f;
            s_bce += (tgt * sp_n + (1.f - tgt) * sp_p) * msk;
            s_m   += msk;
        }
    }

    __shared__ float sb[8], smm[8];
#pragma unroll
    for (int o = 16; o; o >>= 1) {
        s_bce += __shfl_xor_sync(0xFFFFFFFFu, s_bce, o);
        s_m   += __shfl_xor_sync(0xFFFFFFFFu, s_m, o);
    }
    int lane = tid & 31, wid = tid >> 5;
    if (lane == 0) { sb[wid] = s_bce; smm[wid] = s_m; }
    __syncthreads();
    if (tid == 0) {
        float tb = 0.f, tm = 0.f;
#pragma unroll
        for (int i = 0; i < 8; i++) { tb += sb[i]; tm += smm[i]; }
        g_partial[2 * blockIdx.x]     = tb;
        g_partial[2 * blockIdx.x + 1] = tm;
    }
}

__global__ void loss_kernel(float* __restrict__ out) {
    if (threadIdx.x == 0) {
        float tb = 0.f, tm = 0.f;
        for (int i = 0; i < 128; i++) { tb += g_partial[2 * i]; tm += g_partial[2 * i + 1]; }
        out[0] = tb / fmaxf(tm, 1.f);
    }
}

// ============================================================================
extern "C" void kernel_launch(void* const* d_in, const int* in_sizes, int n_in,
                              void* d_out, int out_size) {
    const int*   q_data    = (const int*)d_in[0];
    const int*   qa_data   = (const int*)d_in[1];
    const float* target    = (const float*)d_in[2];
    const float* q_embed   = (const float*)d_in[3];
    const float* qa_embed  = (const float*)d_in[4];
    const float* mem_key   = (const float*)d_in[5];
    const float* mem_val0  = (const float*)d_in[6];
    const float* erase_w   = (const float*)d_in[7];
    const float* erase_b   = (const float*)d_in[8];
    const float* add_w     = (const float*)d_in[9];
    const float* add_b     = (const float*)d_in[10];
    const float* read_w    = (const float*)d_in[11];
    const float* read_b    = (const float*)d_in[12];
    const float* pred_w    = (const float*)d_in[13];
    const float* pred_b    = (const float*)d_in[14];
    float* out = (float*)d_out;

    cudaFuncSetAttribute(scan_kernel, cudaFuncAttributeMaxDynamicSharedMemorySize, 32768);

    transpose_kernel<<<dim3(128, 4), 256>>>(erase_w, add_w, read_w, mem_key);
    w_kernel        <<<BS / 128, 256>>>(q_data, q_embed);
    ea_kernel       <<<dim3(BS / 128, 2), 256>>>(qa_data, qa_embed, erase_b, add_b);
    scan_kernel     <<<B_ * 8, 256, 32768>>>(mem_val0);
    read_pred_kernel<<<BS / 128, 256>>>(q_data, q_embed, read_b, target, pred_w, pred_b, out);
    loss_kernel     <<<1, 32>>>(out);
}

// round 15
// speedup vs baseline: 1.0131x; 1.0131x over previous
#include <cuda_runtime.h>
#include <cuda_bf16.h>
#include <math.h>

#define B_    64
#define S_    256
#define BS    16384
#define M_    64
#define QD_   128
#define QAD_  256
#define VD_   128
#define FD_   128

typedef unsigned long long ull;

// ---------------- scratch ----------------
__device__ float g_w[BS * M_];
__device__ float g_e[BS * VD_];
__device__ float g_a[BS * VD_];
__device__ float g_reads[BS * VD_];
__device__ float g_partial[2 * 128];
__device__ float g_ewT[QAD_ * VD_];    // [256][128]
__device__ float g_awT[QAD_ * VD_];    // [256][128]
__device__ float g_rwT[256 * FD_];     // [256][128]
__device__ float g_keyT[QD_ * M_];     // [128][64]

// ---------------- helpers ----------------
__device__ __forceinline__ ull dup2(float x) {
    ull r; unsigned xi = __float_as_uint(x);
    asm("mov.b64 %0, {%1, %1};" : "=l"(r) : "r"(xi));
    return r;
}
__device__ __forceinline__ ull pack2(float lo, float hi) {
    ull r; unsigned a = __float_as_uint(lo), b = __float_as_uint(hi);
    asm("mov.b64 %0, {%1, %2};" : "=l"(r) : "r"(a), "r"(b));
    return r;
}
__device__ __forceinline__ void unpack2(ull v, float& lo, float& hi) {
    unsigned a, b;
    asm("mov.b64 {%0, %1}, %2;" : "=r"(a), "=r"(b) : "l"(v));
    lo = __uint_as_float(a); hi = __uint_as_float(b);
}
__device__ __forceinline__ void fma2(ull& d, ull a, ull b) {
    asm("fma.rn.f32x2 %0, %1, %2, %0;" : "+l"(d) : "l"(a), "l"(b));
}
__device__ __forceinline__ void cp16(unsigned s, const float* g) {
    asm volatile("cp.async.cg.shared.global [%0], [%1], 16;" :: "r"(s), "l"(g));
}
#define CP_COMMIT() asm volatile("cp.async.commit_group;")
#define CP_WAIT0()  asm volatile("cp.async.wait_group 0;" ::: "memory")

// ============================================================================
// K0: transpose weights into k-major scratch
// ============================================================================
__global__ void transpose_kernel(const float* __restrict__ ew,
                                 const float* __restrict__ aw,
                                 const float* __restrict__ rw,
                                 const float* __restrict__ key) {
    int t = blockIdx.x * 256 + threadIdx.x;
    int which = blockIdx.y;
    if (which < 3) {
        int k = t >> 7, n = t & 127;
        const float* src = which == 0 ? ew : (which == 1 ? aw : rw);
        float* dst = which == 0 ? g_ewT : (which == 1 ? g_awT : g_rwT);
        dst[k * 128 + n] = src[n * 256 + k];
    } else {
        if (t < QD_ * M_) {
            int k = t >> 6, n = t & 63;
            g_keyT[k * 64 + n] = key[n * 128 + k];
        }
    }
}

// ============================================================================
// K1: w = softmax(q_emb @ mem_key^T)
// ============================================================================
__global__ __launch_bounds__(256, 2) void w_kernel(const int* __restrict__ q_data,
                                                   const float* __restrict__ q_w) {
    __shared__ union {
        struct {
            __align__(16) float As[2][16][132];
            __align__(16) float Bs[2][16][68];
        } g;
        float logits[128][65];
    } sm;
    __shared__ int idx_sh[128];

    int tid = threadIdx.x;
    int r0  = blockIdx.x * 128;
    if (tid < 128) idx_sh[tid] = q_data[r0 + tid];
    __syncthreads();

    int tx = tid & 15, ty = tid >> 4;
    int rowL = tid >> 2;
    int kq   = (tid & 3) * 4;

    int bkk = tid >> 4, bcc = (tid & 15) * 4;
    unsigned bs_base = (unsigned)__cvta_generic_to_shared(&sm.g.Bs[0][0][0]);
    unsigned bs_off  = (unsigned)((bkk * 68 + bcc) * 4);
    const unsigned BS_BUF = 16 * 68 * 4;

    ull acc[8][2];
#pragma unroll
    for (int i = 0; i < 8; i++) { acc[i][0] = 0ull; acc[i][1] = 0ull; }

    float4 pa0, pa1;
    pa0 = *(const float4*)(q_w + (long)idx_sh[rowL] * QD_ + kq);
    pa1 = *(const float4*)(q_w + (long)idx_sh[rowL + 64] * QD_ + kq);
    cp16(bs_base + bs_off, g_keyT + bkk * 64 + bcc);
    CP_COMMIT();
    {
        float* a = &sm.g.As[0][kq][0];
        a[0*132+rowL]=pa0.x; a[1*132+rowL]=pa0.y; a[2*132+rowL]=pa0.z; a[3*132+rowL]=pa0.w;
        a[0*132+rowL+64]=pa1.x; a[1*132+rowL+64]=pa1.y; a[2*132+rowL+64]=pa1.z; a[3*132+rowL+64]=pa1.w;
    }
    CP_WAIT0();
    __syncthreads();

    for (int c = 0; c < 8; c++) {
        int cur = c & 1, nb = cur ^ 1;
        if (c + 1 < 8) {
            int k0 = (c + 1) * 16;
            pa0 = *(const float4*)(q_w + (long)idx_sh[rowL] * QD_ + k0 + kq);
            pa1 = *(const float4*)(q_w + (long)idx_sh[rowL + 64] * QD_ + k0 + kq);
            cp16(bs_base + nb * BS_BUF + bs_off, g_keyT + (k0 + bkk) * 64 + bcc);
            CP_COMMIT();
        }
#pragma unroll
        for (int kk = 0; kk < 16; kk++) {
            const float* ap = &sm.g.As[cur][kk][ty * 8];
            float4 a0 = *(const float4*)ap;
            float4 a1 = *(const float4*)(ap + 4);
            ulonglong2 bv = *(const ulonglong2*)&sm.g.Bs[cur][kk][tx * 4];
            ull ad[8] = {dup2(a0.x), dup2(a0.y), dup2(a0.z), dup2(a0.w),
                         dup2(a1.x), dup2(a1.y), dup2(a1.z), dup2(a1.w)};
#pragma unroll
            for (int i = 0; i < 8; i++) {
                fma2(acc[i][0], ad[i], bv.x);
                fma2(acc[i][1], ad[i], bv.y);
            }
        }
        if (c + 1 < 8) {
            float* a = &sm.g.As[nb][kq][0];
            a[0*132+rowL]=pa0.x; a[1*132+rowL]=pa0.y; a[2*132+rowL]=pa0.z; a[3*132+rowL]=pa0.w;
            a[0*132+rowL+64]=pa1.x; a[1*132+rowL+64]=pa1.y; a[2*132+rowL+64]=pa1.z; a[3*132+rowL+64]=pa1.w;
            CP_WAIT0();
        }
        __syncthreads();
    }

#pragma unroll
    for (int i = 0; i < 8; i++) {
        float v0, v1, v2, v3;
        unpack2(acc[i][0], v0, v1);
        unpack2(acc[i][1], v2, v3);
        float* lr = &sm.logits[ty * 8 + i][tx * 4];
        lr[0] = v0; lr[1] = v1; lr[2] = v2; lr[3] = v3;
    }
    __syncthreads();

    int wid = tid >> 5, lane = tid & 31;
    for (int rr = wid; rr < 128; rr += 8) {
        float v0 = sm.logits[rr][lane], v1 = sm.logits[rr][lane + 32];
        float mx = fmaxf(v0, v1);
#pragma unroll
        for (int o = 16; o; o >>= 1) mx = fmaxf(mx, __shfl_xor_sync(0xFFFFFFFFu, mx, o));
        float e0 = __expf(v0 - mx), e1 = __expf(v1 - mx);
        float s = e0 + e1;
#pragma unroll
        for (int o = 16; o; o >>= 1) s += __shfl_xor_sync(0xFFFFFFFFu, s, o);
        float inv = 1.f / s;
        g_w[(r0 + rr) * M_ + lane]      = e0 * inv;
        g_w[(r0 + rr) * M_ + 32 + lane] = e1 * inv;
    }
}

// ============================================================================
// K2: e/a GEMM
// ============================================================================
__global__ __launch_bounds__(256, 2) void ea_kernel(const int* __restrict__ qa_data,
                                                    const float* __restrict__ qa_w,
                                                    const float* __restrict__ eb,
                                                    const float* __restrict__ ab) {
    __shared__ __align__(16) float As[2][16][132];
    __shared__ __align__(16) float Bs[2][16][132];
    __shared__ int idx_sh[128];

    int tid = threadIdx.x;
    int r0  = blockIdx.x * 128;
    int half = blockIdx.y;
    const float* WT   = half ? g_awT : g_ewT;
    const float* bias = half ? ab : eb;
    if (tid < 128) idx_sh[tid] = qa_data[r0 + tid];
    __syncthreads();

    int tx = tid & 15, ty = tid >> 4;
    int rowL = tid >> 2;
    int kq   = (tid & 3) * 4;

    int ch0 = tid, ch1 = tid + 256;
    int bkk0 = ch0 >> 5, bcc0 = (ch0 & 31) * 4;
    int bkk1 = ch1 >> 5, bcc1 = (ch1 & 31) * 4;
    unsigned bs_base = (unsigned)__cvta_generic_to_shared(&Bs[0][0][0]);
    unsigned bo0 = (unsigned)((bkk0 * 132 + bcc0) * 4);
    unsigned bo1 = (unsigned)((bkk1 * 132 + bcc1) * 4);
    const unsigned BS_BUF = 16 * 132 * 4;

    ull acc[8][4];
#pragma unroll
    for (int i = 0; i < 8; i++)
#pragma unroll
        for (int j = 0; j < 4; j++) acc[i][j] = 0ull;

    float4 pa0, pa1;
    pa0 = *(const float4*)(qa_w + (long)idx_sh[rowL] * QAD_ + kq);
    pa1 = *(const float4*)(qa_w + (long)idx_sh[rowL + 64] * QAD_ + kq);
    cp16(bs_base + bo0, WT + bkk0 * 128 + bcc0);
    cp16(bs_base + bo1, WT + bkk1 * 128 + bcc1);
    CP_COMMIT();
    {
        float* a = &As[0][kq][0];
        a[0*132+rowL]=pa0.x; a[1*132+rowL]=pa0.y; a[2*132+rowL]=pa0.z; a[3*132+rowL]=pa0.w;
        a[0*132+rowL+64]=pa1.x; a[1*132+rowL+64]=pa1.y; a[2*132+rowL+64]=pa1.z; a[3*132+rowL+64]=pa1.w;
    }
    CP_WAIT0();
    __syncthreads();

    for (int c = 0; c < 16; c++) {
        int cur = c & 1, nb = cur ^ 1;
        if (c + 1 < 16) {
            int k0 = (c + 1) * 16;
            pa0 = *(const float4*)(qa_w + (long)idx_sh[rowL] * QAD_ + k0 + kq);
            pa1 = *(const float4*)(qa_w + (long)idx_sh[rowL + 64] * QAD_ + k0 + kq);
            cp16(bs_base + nb * BS_BUF + bo0, WT + (k0 + bkk0) * 128 + bcc0);
            cp16(bs_base + nb * BS_BUF + bo1, WT + (k0 + bkk1) * 128 + bcc1);
            CP_COMMIT();
        }
#pragma unroll
        for (int kk = 0; kk < 16; kk++) {
            const float* ap = &As[cur][kk][ty * 8];
            float4 a0 = *(const float4*)ap;
            float4 a1 = *(const float4*)(ap + 4);
            ulonglong2 b01 = *(const ulonglong2*)&Bs[cur][kk][tx * 8];
            ulonglong2 b23 = *(const ulonglong2*)(&Bs[cur][kk][tx * 8] + 4);
            ull ad[8] = {dup2(a0.x), dup2(a0.y), dup2(a0.z), dup2(a0.w),
                         dup2(a1.x), dup2(a1.y), dup2(a1.z), dup2(a1.w)};
#pragma unroll
            for (int i = 0; i < 8; i++) {
                fma2(acc[i][0], ad[i], b01.x);
                fma2(acc[i][1], ad[i], b01.y);
                fma2(acc[i][2], ad[i], b23.x);
                fma2(acc[i][3], ad[i], b23.y);
            }
        }
        if (c + 1 < 16) {
            float* a = &As[nb][kq][0];
            a[0*132+rowL]=pa0.x; a[1*132+rowL]=pa0.y; a[2*132+rowL]=pa0.z; a[3*132+rowL]=pa0.w;
            a[0*132+rowL+64]=pa1.x; a[1*132+rowL+64]=pa1.y; a[2*132+rowL+64]=pa1.z; a[3*132+rowL+64]=pa1.w;
            CP_WAIT0();
        }
        __syncthreads();
    }

    float* dst = half ? g_a : g_e;
#pragma unroll
    for (int i = 0; i < 8; i++) {
        int r = r0 + ty * 8 + i;
        float o[8];
        unpack2(acc[i][0], o[0], o[1]);
        unpack2(acc[i][1], o[2], o[3]);
        unpack2(acc[i][2], o[4], o[5]);
        unpack2(acc[i][3], o[6], o[7]);
        float res[8];
#pragma unroll
        for (int j = 0; j < 8; j++) {
            float x = o[j] + __ldg(bias + tx * 8 + j);
            res[j] = half ? tanhf(x) : (1.f / (1.f + __expf(-x)));
        }
        float4* dp = (float4*)(dst + (long)r * VD_ + tx * 8);
        dp[0] = make_float4(res[0], res[1], res[2], res[3]);
        dp[1] = make_float4(res[4], res[5], res[6], res[7]);
    }
}

// ============================================================================
// K3: sequential memory scan.  256 threads, grid = B_*8 (16 v-cols per block).
//   Smem 96KB: w [256][64] (64KB) + ea [128][64] (32KB) -> 2 blocks/SM.
//   Lane map: 16 mh x 2 vl; thread owns 4 m (2 f32x2).
//   Per 16 steps per warp: 16 LDS.128 (w) + 8 LDS.128 (ea) + 15 SHFL + 1 STG.
// ============================================================================
__global__ __launch_bounds__(256) void scan_kernel(const float* __restrict__ mem_value0) {
    extern __shared__ float smd[];
    float* w_all  = smd;                   // [256][64]  64KB
    float* ea_all = smd + S_ * 64;         // [128][64] 32KB: (t/2)*64 + vloc*4 + (t&1)*2

    int bb = blockIdx.x >> 3, vh = blockIdx.x & 7;   // vh: 16-col slice
    int tid = threadIdx.x;
    int rbase = bb * S_;

    // preload w (contiguous 64KB)
    const float4* wsrc = (const float4*)(g_w + (long)rbase * M_);
    float4* wdst = (float4*)w_all;
    for (int i = tid; i < S_ * M_ / 4; i += 256) wdst[i] = wsrc[i];
    // preload e,a packed 2 steps per 16B (16 cols)
    for (int f = tid; f < S_ * 4; f += 256) {
        int t = f >> 2, c = (f & 3) * 4;
        float4 e4 = *(const float4*)(g_e + (long)(rbase + t) * VD_ + vh * 16 + c);
        float4 a4 = *(const float4*)(g_a + (long)(rbase + t) * VD_ + vh * 16 + c);
        float* base = &ea_all[(t >> 1) * 64 + (t & 1) * 2];
        *(float2*)&base[(c + 0) * 4] = make_float2(e4.x, a4.x);
        *(float2*)&base[(c + 1) * 4] = make_float2(e4.y, a4.y);
        *(float2*)&base[(c + 2) * 4] = make_float2(e4.z, a4.z);
        *(float2*)&base[(c + 3) * 4] = make_float2(e4.w, a4.w);
    }

    int lane = tid & 31, wid = tid >> 5;           // wid 0..7
    int mh = lane & 15, vl = lane >> 4;            // mh 0..15, vl 0..1
    int vloc = wid * 2 + vl;                       // 0..15
    int v = vh * 16 + vloc;
    int mb = mh * 4;                               // 4 m-values per thread

    ull mm[2];
#pragma unroll
    for (int i = 0; i < 2; i++) {
        int m0 = mb + 2 * i;
        mm[i] = pack2(mem_value0[m0 * VD_ + v], mem_value0[(m0 + 1) * VD_ + v]);
    }
    bool b8 = (mh & 8) != 0, b4 = (mh & 4) != 0, b2 = (mh & 2) != 0, b1 = (mh & 1) != 0;
    __syncthreads();

    for (int t0 = 0; t0 < S_; t0 += 16) {
        float p[16];
#pragma unroll
        for (int j = 0; j < 8; j++) {
            // ea for steps t0+2j, t0+2j+1 : one LDS.128
            float4 eab = *(const float4*)&ea_all[((t0 >> 1) + j) * 64 + vloc * 4];
#pragma unroll
            for (int s = 0; s < 2; s++) {
                int u = 2 * j + s;
                float ec = s ? eab.z : eab.x;
                float ac = s ? eab.w : eab.y;
                ull ne2 = dup2(-ec);
                ull a2v = dup2(ac);
                ulonglong2 wA = *(const ulonglong2*)&w_all[(t0 + u) * 64 + mb];
                ull rd2 = 0ull;
#pragma unroll
                for (int i = 0; i < 2; i++) {
                    ull w2 = (i == 0) ? wA.x : wA.y;
                    ull tt = a2v; fma2(tt, ne2, mm[i]);   // a - e*mem
                    fma2(rd2, w2, mm[i]);                 // read uses old mem
                    fma2(mm[i], w2, tt);                  // mem += w*(a - e*mem)
                }
                float rl, rh; unpack2(rd2, rl, rh);
                p[u] = rl + rh;
            }
        }

        // reduce-scatter across 16 mh-lanes: 15 shfls; thread ends owning step t0+mh.
        float q8[8];
#pragma unroll
        for (int x = 0; x < 8; x++) {
            float send = b8 ? p[x] : p[x + 8];
            float recv = __shfl_xor_sync(0xFFFFFFFFu, send, 8);
            q8[x] = (b8 ? p[x + 8] : p[x]) + recv;
        }
        float q4[4];
#pragma unroll
        for (int x = 0; x < 4; x++) {
            float send = b4 ? q8[x] : q8[x + 4];
            float recv = __shfl_xor_sync(0xFFFFFFFFu, send, 4);
            q4[x] = (b4 ? q8[x + 4] : q8[x]) + recv;
        }
        float q2[2];
#pragma unroll
        for (int x = 0; x < 2; x++) {
            float send = b2 ? q4[x] : q4[x + 2];
            float recv = __shfl_xor_sync(0xFFFFFFFFu, send, 2);
            q2[x] = (b2 ? q4[x + 2] : q4[x]) + recv;
        }
        {
            float send = b1 ? q2[0] : q2[1];
            float recv = __shfl_xor_sync(0xFFFFFFFFu, send, 1);
            float rd = (b1 ? q2[1] : q2[0]) + recv;
            g_reads[(long)(rbase + t0 + mh) * VD_ + v] = rd;
        }
    }
}

// ============================================================================
// K4: h = tanh([reads,q_emb] @ rwT + rb) fused with pred + BCE.
// ============================================================================
__global__ __launch_bounds__(256, 2) void read_pred_kernel(const int* __restrict__ q_data,
                                                           const float* __restrict__ q_w,
                                                           const float* __restrict__ rb,
                                                           const float* __restrict__ target,
                                                           const float* __restrict__ pw,
                                                           const float* __restrict__ pb,
                                                           float* __restrict__ out) {
    __shared__ __align__(16) float As[2][16][132];
    __shared__ __align__(16) float Bs[2][16][132];
    __shared__ int idx_sh[128];

    int tid = threadIdx.x;
    int r0  = blockIdx.x * 128;
    if (tid < 128) idx_sh[tid] = q_data[r0 + tid];
    __syncthreads();

    int tx = tid & 15, ty = tid >> 4;
    int rowL = tid >> 2;
    int kq   = (tid & 3) * 4;

    int ch0 = tid, ch1 = tid + 256;
    int bkk0 = ch0 >> 5, bcc0 = (ch0 & 31) * 4;
    int bkk1 = ch1 >> 5, bcc1 = (ch1 & 31) * 4;
    unsigned bs_base = (unsigned)__cvta_generic_to_shared(&Bs[0][0][0]);
    unsigned bo0 = (unsigned)((bkk0 * 132 + bcc0) * 4);
    unsigned bo1 = (unsigned)((bkk1 * 132 + bcc1) * 4);
    const unsigned BS_BUF = 16 * 132 * 4;

    ull acc[8][4];
#pragma unroll
    for (int i = 0; i < 8; i++)
#pragma unroll
        for (int j = 0; j < 4; j++) acc[i][j] = 0ull;

    float4 pa0, pa1;
    pa0 = *(const float4*)(g_reads + (long)(r0 + rowL) * VD_ + kq);
    pa1 = *(const float4*)(g_reads + (long)(r0 + rowL + 64) * VD_ + kq);
    cp16(bs_base + bo0, g_rwT + bkk0 * 128 + bcc0);
    cp16(bs_base + bo1, g_rwT + bkk1 * 128 + bcc1);
    CP_COMMIT();
    {
        float* a = &As[0][kq][0];
        a[0*132+rowL]=pa0.x; a[1*132+rowL]=pa0.y; a[2*132+rowL]=pa0.z; a[3*132+rowL]=pa0.w;
        a[0*132+rowL+64]=pa1.x; a[1*132+rowL+64]=pa1.y; a[2*132+rowL+64]=pa1.z; a[3*132+rowL+64]=pa1.w;
    }
    CP_WAIT0();
    __syncthreads();

    for (int c = 0; c < 16; c++) {
        int cur = c & 1, nb = cur ^ 1;
        if (c + 1 < 16) {
            int k0 = (c + 1) * 16;
            if (k0 < 128) {
                pa0 = *(const float4*)(g_reads + (long)(r0 + rowL) * VD_ + k0 + kq);
                pa1 = *(const float4*)(g_reads + (long)(r0 + rowL + 64) * VD_ + k0 + kq);
            } else {
                pa0 = *(const float4*)(q_w + (long)idx_sh[rowL] * QD_ + (k0 - 128) + kq);
                pa1 = *(const float4*)(q_w + (long)idx_sh[rowL + 64] * QD_ + (k0 - 128) + kq);
            }
            cp16(bs_base + nb * BS_BUF + bo0, g_rwT + (k0 + bkk0) * 128 + bcc0);
            cp16(bs_base + nb * BS_BUF + bo1, g_rwT + (k0 + bkk1) * 128 + bcc1);
            CP_COMMIT();
        }
#pragma unroll
        for (int kk = 0; kk < 16; kk++) {
            const float* ap = &As[cur][kk][ty * 8];
            float4 a0 = *(const float4*)ap;
            float4 a1 = *(const float4*)(ap + 4);
            ulonglong2 b01 = *(const ulonglong2*)&Bs[cur][kk][tx * 8];
            ulonglong2 b23 = *(const ulonglong2*)(&Bs[cur][kk][tx * 8] + 4);
            ull ad[8] = {dup2(a0.x), dup2(a0.y), dup2(a0.z), dup2(a0.w),
                         dup2(a1.x), dup2(a1.y), dup2(a1.z), dup2(a1.w)};
#pragma unroll
            for (int i = 0; i < 8; i++) {
                fma2(acc[i][0], ad[i], b01.x);
                fma2(acc[i][1], ad[i], b01.y);
                fma2(acc[i][2], ad[i], b23.x);
                fma2(acc[i][3], ad[i], b23.y);
            }
        }
        if (c + 1 < 16) {
            float* a = &As[nb][kq][0];
            a[0*132+rowL]=pa0.x; a[1*132+rowL]=pa0.y; a[2*132+rowL]=pa0.z; a[3*132+rowL]=pa0.w;
            a[0*132+rowL+64]=pa1.x; a[1*132+rowL+64]=pa1.y; a[2*132+rowL+64]=pa1.z; a[3*132+rowL+64]=pa1.w;
            CP_WAIT0();
        }
        __syncthreads();
    }

    float pbv = __ldg(pb);
    float s_bce = 0.f, s_m = 0.f;
#pragma unroll
    for (int i = 0; i < 8; i++) {
        int r = r0 + ty * 8 + i;
        float o[8];
        unpack2(acc[i][0], o[0], o[1]);
        unpack2(acc[i][1], o[2], o[3]);
        unpack2(acc[i][2], o[4], o[5]);
        unpack2(acc[i][3], o[6], o[7]);
        float part = 0.f;
#pragma unroll
        for (int j = 0; j < 8; j++) {
            int vv = tx * 8 + j;
            float hv = tanhf(o[j] + __ldg(rb + vv));
            part = fmaf(hv, __ldg(pw + vv), part);
        }
        part += __shfl_xor_sync(0xFFFFFFFFu, part, 1);
        part += __shfl_xor_sync(0xFFFFFFFFu, part, 2);
        part += __shfl_xor_sync(0xFFFFFFFFu, part, 4);
        part += __shfl_xor_sync(0xFFFFFFFFu, part, 8);
        if (tx == 0) {
            float logit = part + pbv;
            float pred = 1.f / (1.f + __expf(-logit));
            float tgt  = target[r];
            out[1 + r]      = pred;
            out[1 + BS + r] = tgt;
            float spa = log1pf(__expf(-fabsf(logit)));
            float sp_n = fmaxf(-logit, 0.f) + spa;
            float sp_p = fmaxf(logit, 0.f) + spa;
            float msk = (tgt >= 0.f) ? 1.f : 0.f;
            s_bce += (tgt * sp_n + (1.f - tgt) * sp_p) * msk;
            s_m   += msk;
        }
    }

    __shared__ float sb[8], smm[8];
#pragma unroll
    for (int o = 16; o; o >>= 1) {
        s_bce += __shfl_xor_sync(0xFFFFFFFFu, s_bce, o);
        s_m   += __shfl_xor_sync(0xFFFFFFFFu, s_m, o);
    }
    int lane = tid & 31, wid = tid >> 5;
    if (lane == 0) { sb[wid] = s_bce; smm[wid] = s_m; }
    __syncthreads();
    if (tid == 0) {
        float tb = 0.f, tm = 0.f;
#pragma unroll
        for (int i = 0; i < 8; i++) { tb += sb[i]; tm += smm[i]; }
        g_partial[2 * blockIdx.x]     = tb;
        g_partial[2 * blockIdx.x + 1] = tm;
    }
}

__global__ void loss_kernel(float* __restrict__ out) {
    if (threadIdx.x == 0) {
        float tb = 0.f, tm = 0.f;
        for (int i = 0; i < 128; i++) { tb += g_partial[2 * i]; tm += g_partial[2 * i + 1]; }
        out[0] = tb / fmaxf(tm, 1.f);
    }
}

// ============================================================================
extern "C" void kernel_launch(void* const* d_in, const int* in_sizes, int n_in,
                              void* d_out, int out_size) {
    const int*   q_data    = (const int*)d_in[0];
    const int*   qa_data   = (const int*)d_in[1];
    const float* target    = (const float*)d_in[2];
    const float* q_embed   = (const float*)d_in[3];
    const float* qa_embed  = (const float*)d_in[4];
    const float* mem_key   = (const float*)d_in[5];
    const float* mem_val0  = (const float*)d_in[6];
    const float* erase_w   = (const float*)d_in[7];
    const float* erase_b   = (const float*)d_in[8];
    const float* add_w     = (const float*)d_in[9];
    const float* add_b     = (const float*)d_in[10];
    const float* read_w    = (const float*)d_in[11];
    const float* read_b    = (const float*)d_in[12];
    const float* pred_w    = (const float*)d_in[13];
    const float* pred_b    = (const float*)d_in[14];
    float* out = (float*)d_out;

    cudaFuncSetAttribute(scan_kernel, cudaFuncAttributeMaxDynamicSharedMemorySize, 98304);

    transpose_kernel<<<dim3(128, 4), 256>>>(erase_w, add_w, read_w, mem_key);
    w_kernel        <<<BS / 128, 256>>>(q_data, q_embed);
    ea_kernel       <<<dim3(BS / 128, 2), 256>>>(qa_data, qa_embed, erase_b, add_b);
    scan_kernel     <<<B_ * 8, 256, 98304>>>(mem_val0);
    read_pred_kernel<<<BS / 128, 256>>>(q_data, q_embed, read_b, target, pred_w, pred_b, out);
    loss_kernel     <<<1, 32>>>(out);
}

// round 16
// speedup vs baseline: 1.3500x; 1.3326x over previous
#include <cuda_runtime.h>
#include <cuda_bf16.h>
#include <math.h>

#define B_    64
#define S_    256
#define BS    16384
#define M_    64
#define QD_   128
#define QAD_  256
#define VD_   128
#define FD_   128

typedef unsigned long long ull;

// ---------------- scratch ----------------
__device__ float g_w[BS * M_];
__device__ float g_e[BS * VD_];
__device__ float g_a[BS * VD_];
__device__ float g_reads[BS * VD_];
__device__ float g_partial[2 * 128];
__device__ float g_Bfrag[8 * 32 * 2 * 32 * 4];  // tf32 fragment-permuted [kb][nt(32=e16,a16)][kp][lane][4]
__device__ float g_rwT[256 * FD_];              // [256][128]
__device__ float g_keyT[QD_ * M_];              // [128][64]

// ---------------- helpers ----------------
__device__ __forceinline__ ull dup2(float x) {
    ull r; unsigned xi = __float_as_uint(x);
    asm("mov.b64 %0, {%1, %1};" : "=l"(r) : "r"(xi));
    return r;
}
__device__ __forceinline__ ull pack2(float lo, float hi) {
    ull r; unsigned a = __float_as_uint(lo), b = __float_as_uint(hi);
    asm("mov.b64 %0, {%1, %2};" : "=l"(r) : "r"(a), "r"(b));
    return r;
}
__device__ __forceinline__ void unpack2(ull v, float& lo, float& hi) {
    unsigned a, b;
    asm("mov.b64 {%0, %1}, %2;" : "=r"(a), "=r"(b) : "l"(v));
    lo = __uint_as_float(a); hi = __uint_as_float(b);
}
__device__ __forceinline__ void fma2(ull& d, ull a, ull b) {
    asm("fma.rn.f32x2 %0, %1, %2, %0;" : "+l"(d) : "l"(a), "l"(b));
}
__device__ __forceinline__ void cp16(unsigned s, const float* g) {
    asm volatile("cp.async.cg.shared.global [%0], [%1], 16;" :: "r"(s), "l"(g));
}
#define CP_COMMIT() asm volatile("cp.async.commit_group;")
#define CP_WAIT0()  asm volatile("cp.async.wait_group 0;" ::: "memory")

__device__ __forceinline__ unsigned tf32cvt(float f) {
    unsigned u; asm("cvt.rna.tf32.f32 %0, %1;" : "=r"(u) : "f"(f));
    return u;
}
__device__ __forceinline__ void sts32(unsigned addr, unsigned v) {
    asm volatile("st.shared.b32 [%0], %1;" :: "r"(addr), "r"(v));
}
__device__ __forceinline__ void lds128(uint4& d, unsigned addr) {
    asm volatile("ld.shared.v4.b32 {%0,%1,%2,%3}, [%4];"
                 : "=r"(d.x), "=r"(d.y), "=r"(d.z), "=r"(d.w) : "r"(addr));
}
__device__ __forceinline__ void mma_tf32(float* d, const unsigned* a, unsigned b0, unsigned b1) {
    asm volatile("mma.sync.aligned.m16n8k8.row.col.f32.tf32.tf32.f32 "
                 "{%0,%1,%2,%3}, {%4,%5,%6,%7}, {%8,%9}, {%0,%1,%2,%3};"
                 : "+f"(d[0]), "+f"(d[1]), "+f"(d[2]), "+f"(d[3])
                 : "r"(a[0]), "r"(a[1]), "r"(a[2]), "r"(a[3]), "r"(b0), "r"(b1));
}

// ============================================================================
// K0: weight prep.  which 0/1: erase/add -> tf32 fragment-permuted g_Bfrag.
//     which 2: read_w -> g_rwT transpose.  which 3: mem_key -> g_keyT.
// ============================================================================
__global__ void transpose_kernel(const float* __restrict__ ew,
                                 const float* __restrict__ aw,
                                 const float* __restrict__ rw,
                                 const float* __restrict__ key) {
    int t = blockIdx.x * 256 + threadIdx.x;
    int which = blockIdx.y;
    if (which < 2) {
        int n = t >> 8, k = t & 255;           // n: out col 0..127, k: 0..255
        const float* src = which == 0 ? ew : aw;
        unsigned uv = tf32cvt(src[n * 256 + k]);
        int kb = k >> 5, ks = (k >> 3) & 3, kp = ks >> 1, par = ks & 1;
        int k8 = k & 7, tt = k8 & 3, j = k8 >> 2;
        int ntg = which * 16 + (n >> 3), g = n & 7;
        int lanef = g * 4 + tt, reg = par * 2 + j;
        int off = (((kb * 32 + ntg) * 2 + kp) * 32 + lanef) * 4 + reg;
        ((unsigned*)g_Bfrag)[off] = uv;
    } else if (which == 2) {
        int k = t >> 7, n = t & 127;
        g_rwT[k * 128 + n] = rw[n * 256 + k];
    } else {
        if (t < QD_ * M_) {
            int k = t >> 6, n = t & 63;
            g_keyT[k * 64 + n] = key[n * 128 + k];
        }
    }
}

// ============================================================================
// K1: w = softmax(q_emb @ mem_key^T)
// ============================================================================
__global__ __launch_bounds__(256, 2) void w_kernel(const int* __restrict__ q_data,
                                                   const float* __restrict__ q_w) {
    __shared__ union {
        struct {
            __align__(16) float As[2][16][132];
            __align__(16) float Bs[2][16][68];
        } g;
        float logits[128][65];
    } sm;
    __shared__ int idx_sh[128];

    int tid = threadIdx.x;
    int r0  = blockIdx.x * 128;
    if (tid < 128) idx_sh[tid] = q_data[r0 + tid];
    __syncthreads();

    int tx = tid & 15, ty = tid >> 4;
    int rowL = tid >> 2;
    int kq   = (tid & 3) * 4;

    int bkk = tid >> 4, bcc = (tid & 15) * 4;
    unsigned bs_base = (unsigned)__cvta_generic_to_shared(&sm.g.Bs[0][0][0]);
    unsigned bs_off  = (unsigned)((bkk * 68 + bcc) * 4);
    const unsigned BS_BUF = 16 * 68 * 4;

    ull acc[8][2];
#pragma unroll
    for (int i = 0; i < 8; i++) { acc[i][0] = 0ull; acc[i][1] = 0ull; }

    float4 pa0, pa1;
    pa0 = *(const float4*)(q_w + (long)idx_sh[rowL] * QD_ + kq);
    pa1 = *(const float4*)(q_w + (long)idx_sh[rowL + 64] * QD_ + kq);
    cp16(bs_base + bs_off, g_keyT + bkk * 64 + bcc);
    CP_COMMIT();
    {
        float* a = &sm.g.As[0][kq][0];
        a[0*132+rowL]=pa0.x; a[1*132+rowL]=pa0.y; a[2*132+rowL]=pa0.z; a[3*132+rowL]=pa0.w;
        a[0*132+rowL+64]=pa1.x; a[1*132+rowL+64]=pa1.y; a[2*132+rowL+64]=pa1.z; a[3*132+rowL+64]=pa1.w;
    }
    CP_WAIT0();
    __syncthreads();

    for (int c = 0; c < 8; c++) {
        int cur = c & 1, nb = cur ^ 1;
        if (c + 1 < 8) {
            int k0 = (c + 1) * 16;
            pa0 = *(const float4*)(q_w + (long)idx_sh[rowL] * QD_ + k0 + kq);
            pa1 = *(const float4*)(q_w + (long)idx_sh[rowL + 64] * QD_ + k0 + kq);
            cp16(bs_base + nb * BS_BUF + bs_off, g_keyT + (k0 + bkk) * 64 + bcc);
            CP_COMMIT();
        }
#pragma unroll
        for (int kk = 0; kk < 16; kk++) {
            const float* ap = &sm.g.As[cur][kk][ty * 8];
            float4 a0 = *(const float4*)ap;
            float4 a1 = *(const float4*)(ap + 4);
            ulonglong2 bv = *(const ulonglong2*)&sm.g.Bs[cur][kk][tx * 4];
            ull ad[8] = {dup2(a0.x), dup2(a0.y), dup2(a0.z), dup2(a0.w),
                         dup2(a1.x), dup2(a1.y), dup2(a1.z), dup2(a1.w)};
#pragma unroll
            for (int i = 0; i < 8; i++) {
                fma2(acc[i][0], ad[i], bv.x);
                fma2(acc[i][1], ad[i], bv.y);
            }
        }
        if (c + 1 < 8) {
            float* a = &sm.g.As[nb][kq][0];
            a[0*132+rowL]=pa0.x; a[1*132+rowL]=pa0.y; a[2*132+rowL]=pa0.z; a[3*132+rowL]=pa0.w;
            a[0*132+rowL+64]=pa1.x; a[1*132+rowL+64]=pa1.y; a[2*132+rowL+64]=pa1.z; a[3*132+rowL+64]=pa1.w;
            CP_WAIT0();
        }
        __syncthreads();
    }

#pragma unroll
    for (int i = 0; i < 8; i++) {
        float v0, v1, v2, v3;
        unpack2(acc[i][0], v0, v1);
        unpack2(acc[i][1], v2, v3);
        float* lr = &sm.logits[ty * 8 + i][tx * 4];
        lr[0] = v0; lr[1] = v1; lr[2] = v2; lr[3] = v3;
    }
    __syncthreads();

    int wid = tid >> 5, lane = tid & 31;
    for (int rr = wid; rr < 128; rr += 8) {
        float v0 = sm.logits[rr][lane], v1 = sm.logits[rr][lane + 32];
        float mx = fmaxf(v0, v1);
#pragma unroll
        for (int o = 16; o; o >>= 1) mx = fmaxf(mx, __shfl_xor_sync(0xFFFFFFFFu, mx, o));
        float e0 = __expf(v0 - mx), e1 = __expf(v1 - mx);
        float s = e0 + e1;
#pragma unroll
        for (int o = 16; o; o >>= 1) s += __shfl_xor_sync(0xFFFFFFFFu, s, o);
        float inv = 1.f / s;
        g_w[(r0 + rr) * M_ + lane]      = e0 * inv;
        g_w[(r0 + rr) * M_ + 32 + lane] = e1 * inv;
    }
}

// ============================================================================
// K2: e/a via tf32 mma.  512 threads = 16 warps (4 m x 4 n over N=256 concat).
//   BM=128, BK=32, 8 k-blocks.  Smem 96KB: Afrag 2x16KB + Bfrag 2x32KB.
// ============================================================================
__global__ __launch_bounds__(512, 1) void ea_kernel(const int* __restrict__ qa_data,
                                                    const float* __restrict__ qa_w,
                                                    const float* __restrict__ eb,
                                                    const float* __restrict__ ab) {
    extern __shared__ float eas[];
    float* Af = eas;                 // [2][4096]
    float* Bf = eas + 8192;          // [2][8192]
    __shared__ int idx_sh[128];

    int tid = threadIdx.x;
    int r0  = blockIdx.x * 128;
    if (tid < 128) idx_sh[tid] = qa_data[r0 + tid];
    __syncthreads();

    int lane = tid & 31, wid = tid >> 5;
    int warp_m = wid & 3, warp_n = wid >> 2;

    unsigned sA = (unsigned)__cvta_generic_to_shared(Af);
    unsigned sB = (unsigned)__cvta_generic_to_shared(Bf);
    const unsigned A_BUF = 4096 * 4, B_BUF = 8192 * 4;

    // A staging: 2 quartets per thread (row, 4 consecutive k)
    int q0 = tid, q1 = tid + 512;
    int row0 = q0 >> 3, kq0 = q0 & 7;
    int row1 = q1 >> 3, kq1 = q1 & 7;
    const float* arow0 = qa_w + (long)idx_sh[row0] * QAD_;
    const float* arow1 = qa_w + (long)idx_sh[row1] * QAD_;

    // precompute A fragment STS byte-offsets (constant across kb)
    unsigned offA[2][4];
#pragma unroll
    for (int qq = 0; qq < 2; qq++) {
        int row = qq ? row1 : row0, kqv = qq ? kq1 : kq0;
        int mt = row >> 4, r16 = row & 15, g = r16 & 7, im = r16 >> 3;
#pragma unroll
        for (int cc = 0; cc < 4; cc++) {
            int cl = kqv * 4 + cc;
            int ks = cl >> 3, k8 = cl & 7, tt = k8 & 3, j = k8 >> 2;
            int lanef = g * 4 + tt, reg = im + 2 * j;
            offA[qq][cc] = (unsigned)((((mt * 4 + ks) * 32 + lanef) * 4 + reg) * 4);
        }
    }

    float acc[2][8][4];
#pragma unroll
    for (int i = 0; i < 2; i++)
#pragma unroll
        for (int j = 0; j < 8; j++)
#pragma unroll
            for (int k = 0; k < 4; k++) acc[i][j][k] = 0.f;

    // prologue: kb = 0
    float4 av0 = *(const float4*)(arow0 + kq0 * 4);
    float4 av1 = *(const float4*)(arow1 + kq1 * 4);
#pragma unroll
    for (int ci = 0; ci < 4; ci++) {
        int c = tid + 512 * ci;
        cp16(sB + c * 16, g_Bfrag + c * 4);
    }
    CP_COMMIT();
    sts32(sA + offA[0][0], tf32cvt(av0.x)); sts32(sA + offA[0][1], tf32cvt(av0.y));
    sts32(sA + offA[0][2], tf32cvt(av0.z)); sts32(sA + offA[0][3], tf32cvt(av0.w));
    sts32(sA + offA[1][0], tf32cvt(av1.x)); sts32(sA + offA[1][1], tf32cvt(av1.y));
    sts32(sA + offA[1][2], tf32cvt(av1.z)); sts32(sA + offA[1][3], tf32cvt(av1.w));
    CP_WAIT0();
    __syncthreads();

    for (int kb = 0; kb < 8; kb++) {
        int cur = kb & 1, nb = cur ^ 1;
        if (kb + 1 < 8) {
            av0 = *(const float4*)(arow0 + (kb + 1) * 32 + kq0 * 4);
            av1 = *(const float4*)(arow1 + (kb + 1) * 32 + kq1 * 4);
#pragma unroll
            for (int ci = 0; ci < 4; ci++) {
                int c = tid + 512 * ci;
                cp16(sB + nb * B_BUF + c * 16, g_Bfrag + (kb + 1) * 8192 + c * 4);
            }
            CP_COMMIT();
        }
        unsigned aB = sA + cur * A_BUF;
        unsigned bB = sB + cur * B_BUF;
#pragma unroll
        for (int kp = 0; kp < 2; kp++) {
            uint4 afr[2][2];
#pragma unroll
            for (int mtl = 0; mtl < 2; mtl++)
#pragma unroll
                for (int par = 0; par < 2; par++) {
                    int mt = warp_m * 2 + mtl, ks = kp * 2 + par;
                    lds128(afr[mtl][par], aB + (unsigned)(((mt * 4 + ks) * 32 + lane) * 16));
                }
#pragma unroll
            for (int ntl = 0; ntl < 8; ntl++) {
                int nt = warp_n * 8 + ntl;
                uint4 bfr;
                lds128(bfr, bB + (unsigned)(((nt * 2 + kp) * 32 + lane) * 16));
#pragma unroll
                for (int mtl = 0; mtl < 2; mtl++) {
                    mma_tf32(acc[mtl][ntl], (const unsigned*)&afr[mtl][0], bfr.x, bfr.y);
                    mma_tf32(acc[mtl][ntl], (const unsigned*)&afr[mtl][1], bfr.z, bfr.w);
                }
            }
        }
        if (kb + 1 < 8) {
            unsigned aN = sA + nb * A_BUF;
            sts32(aN + offA[0][0], tf32cvt(av0.x)); sts32(aN + offA[0][1], tf32cvt(av0.y));
            sts32(aN + offA[0][2], tf32cvt(av0.z)); sts32(aN + offA[0][3], tf32cvt(av0.w));
            sts32(aN + offA[1][0], tf32cvt(av1.x)); sts32(aN + offA[1][1], tf32cvt(av1.y));
            sts32(aN + offA[1][2], tf32cvt(av1.z)); sts32(aN + offA[1][3], tf32cvt(av1.w));
            CP_WAIT0();
        }
        __syncthreads();
    }

    // epilogue
    int matrix = warp_n >> 1;
    int colb = (warp_n & 1) * 64;
    float* dst = matrix ? g_a : g_e;
    const float* bias = matrix ? ab : eb;
    int g = lane >> 2, t2 = (lane & 3) * 2;
#pragma unroll
    for (int ntl = 0; ntl < 8; ntl++) {
        int col = colb + ntl * 8 + t2;
        float b0v = __ldg(bias + col), b1v = __ldg(bias + col + 1);
#pragma unroll
        for (int mtl = 0; mtl < 2; mtl++) {
            int rowb = r0 + warp_m * 32 + mtl * 16 + g;
            float x0 = acc[mtl][ntl][0] + b0v, x1 = acc[mtl][ntl][1] + b1v;
            float x2 = acc[mtl][ntl][2] + b0v, x3 = acc[mtl][ntl][3] + b1v;
            float y0, y1, y2, y3;
            if (matrix) {
                y0 = tanhf(x0); y1 = tanhf(x1); y2 = tanhf(x2); y3 = tanhf(x3);
            } else {
                y0 = 1.f / (1.f + __expf(-x0)); y1 = 1.f / (1.f + __expf(-x1));
                y2 = 1.f / (1.f + __expf(-x2)); y3 = 1.f / (1.f + __expf(-x3));
            }
            *(float2*)(dst + (long)rowb * VD_ + col) = make_float2(y0, y1);
            *(float2*)(dst + (long)(rowb + 8) * VD_ + col) = make_float2(y2, y3);
        }
    }
}

// ============================================================================
// K3: sequential memory scan (R13 config: grid B_*4, 512 thr, 128KB smem).
// ============================================================================
__global__ __launch_bounds__(512) void scan_kernel(const float* __restrict__ mem_value0) {
    extern __shared__ float smd[];
    float* w_all  = smd;                   // [256][64]  64KB
    float* ea_all = smd + S_ * 64;         // [128][128] 64KB

    int bb = blockIdx.x >> 2, vh = blockIdx.x & 3;
    int tid = threadIdx.x;
    int rbase = bb * S_;

    const float4* wsrc = (const float4*)(g_w + (long)rbase * M_);
    float4* wdst = (float4*)w_all;
    for (int i = tid; i < S_ * M_ / 4; i += 512) wdst[i] = wsrc[i];
    for (int f = tid; f < S_ * 8; f += 512) {
        int t = f >> 3, c = (f & 7) * 4;
        float4 e4 = *(const float4*)(g_e + (long)(rbase + t) * VD_ + vh * 32 + c);
        float4 a4 = *(const float4*)(g_a + (long)(rbase + t) * VD_ + vh * 32 + c);
        float* base = &ea_all[(t >> 1) * 128 + (t & 1) * 2];
        *(float2*)&base[(c + 0) * 4] = make_float2(e4.x, a4.x);
        *(float2*)&base[(c + 1) * 4] = make_float2(e4.y, a4.y);
        *(float2*)&base[(c + 2) * 4] = make_float2(e4.z, a4.z);
        *(float2*)&base[(c + 3) * 4] = make_float2(e4.w, a4.w);
    }

    int lane = tid & 31, wid = tid >> 5;
    int mh = lane & 15, vl = lane >> 4;
    int vloc = wid * 2 + vl;               // 0..31
    int v = vh * 32 + vloc;
    int mb = mh * 4;

    ull mm[2];
#pragma unroll
    for (int i = 0; i < 2; i++) {
        int m0 = mb + 2 * i;
        mm[i] = pack2(mem_value0[m0 * VD_ + v], mem_value0[(m0 + 1) * VD_ + v]);
    }
    bool b8 = (mh & 8) != 0, b4 = (mh & 4) != 0, b2 = (mh & 2) != 0, b1 = (mh & 1) != 0;
    __syncthreads();

    for (int t0 = 0; t0 < S_; t0 += 16) {
        float p[16];
#pragma unroll
        for (int j = 0; j < 8; j++) {
            float4 eab = *(const float4*)&ea_all[((t0 >> 1) + j) * 128 + vloc * 4];
#pragma unroll
            for (int s = 0; s < 2; s++) {
                int u = 2 * j + s;
                float ec = s ? eab.z : eab.x;
                float ac = s ? eab.w : eab.y;
                ull ne2 = dup2(-ec);
                ull a2v = dup2(ac);
                ulonglong2 wA = *(const ulonglong2*)&w_all[(t0 + u) * 64 + mb];
                ull rd2 = 0ull;
#pragma unroll
                for (int i = 0; i < 2; i++) {
                    ull w2 = (i == 0) ? wA.x : wA.y;
                    ull tt = a2v; fma2(tt, ne2, mm[i]);
                    fma2(rd2, w2, mm[i]);
                    fma2(mm[i], w2, tt);
                }
                float rl, rh; unpack2(rd2, rl, rh);
                p[u] = rl + rh;
            }
        }

        float q8[8];
#pragma unroll
        for (int x = 0; x < 8; x++) {
            float send = b8 ? p[x] : p[x + 8];
            float recv = __shfl_xor_sync(0xFFFFFFFFu, send, 8);
            q8[x] = (b8 ? p[x + 8] : p[x]) + recv;
        }
        float q4[4];
#pragma unroll
        for (int x = 0; x < 4; x++) {
            float send = b4 ? q8[x] : q8[x + 4];
            float recv = __shfl_xor_sync(0xFFFFFFFFu, send, 4);
            q4[x] = (b4 ? q8[x + 4] : q8[x]) + recv;
        }
        float q2[2];
#pragma unroll
        for (int x = 0; x < 2; x++) {
            float send = b2 ? q4[x] : q4[x + 2];
            float recv = __shfl_xor_sync(0xFFFFFFFFu, send, 2);
            q2[x] = (b2 ? q4[x + 2] : q4[x]) + recv;
        }
        {
            float send = b1 ? q2[0] : q2[1];
            float recv = __shfl_xor_sync(0xFFFFFFFFu, send, 1);
            float rd = (b1 ? q2[1] : q2[0]) + recv;
            g_reads[(long)(rbase + t0 + mh) * VD_ + v] = rd;
        }
    }
}

// ============================================================================
// K4: h = tanh([reads,q_emb] @ rwT + rb) fused with pred + BCE.
// ============================================================================
__global__ __launch_bounds__(256, 2) void read_pred_kernel(const int* __restrict__ q_data,
                                                           const float* __restrict__ q_w,
                                                           const float* __restrict__ rb,
                                                           const float* __restrict__ target,
                                                           const float* __restrict__ pw,
                                                           const float* __restrict__ pb,
                                                           float* __restrict__ out) {
    __shared__ __align__(16) float As[2][16][132];
    __shared__ __align__(16) float Bs[2][16][132];
    __shared__ int idx_sh[128];

    int tid = threadIdx.x;
    int r0  = blockIdx.x * 128;
    if (tid < 128) idx_sh[tid] = q_data[r0 + tid];
    __syncthreads();

    int tx = tid & 15, ty = tid >> 4;
    int rowL = tid >> 2;
    int kq   = (tid & 3) * 4;

    int ch0 = tid, ch1 = tid + 256;
    int bkk0 = ch0 >> 5, bcc0 = (ch0 & 31) * 4;
    int bkk1 = ch1 >> 5, bcc1 = (ch1 & 31) * 4;
    unsigned bs_base = (unsigned)__cvta_generic_to_shared(&Bs[0][0][0]);
    unsigned bo0 = (unsigned)((bkk0 * 132 + bcc0) * 4);
    unsigned bo1 = (unsigned)((bkk1 * 132 + bcc1) * 4);
    const unsigned BS_BUF = 16 * 132 * 4;

    ull acc[8][4];
#pragma unroll
    for (int i = 0; i < 8; i++)
#pragma unroll
        for (int j = 0; j < 4; j++) acc[i][j] = 0ull;

    float4 pa0, pa1;
    pa0 = *(const float4*)(g_reads + (long)(r0 + rowL) * VD_ + kq);
    pa1 = *(const float4*)(g_reads + (long)(r0 + rowL + 64) * VD_ + kq);
    cp16(bs_base + bo0, g_rwT + bkk0 * 128 + bcc0);
    cp16(bs_base + bo1, g_rwT + bkk1 * 128 + bcc1);
    CP_COMMIT();
    {
        float* a = &As[0][kq][0];
        a[0*132+rowL]=pa0.x; a[1*132+rowL]=pa0.y; a[2*132+rowL]=pa0.z; a[3*132+rowL]=pa0.w;
        a[0*132+rowL+64]=pa1.x; a[1*132+rowL+64]=pa1.y; a[2*132+rowL+64]=pa1.z; a[3*132+rowL+64]=pa1.w;
    }
    CP_WAIT0();
    __syncthreads();

    for (int c = 0; c < 16; c++) {
        int cur = c & 1, nb = cur ^ 1;
        if (c + 1 < 16) {
            int k0 = (c + 1) * 16;
            if (k0 < 128) {
                pa0 = *(const float4*)(g_reads + (long)(r0 + rowL) * VD_ + k0 + kq);
                pa1 = *(const float4*)(g_reads + (long)(r0 + rowL + 64) * VD_ + k0 + kq);
            } else {
                pa0 = *(const float4*)(q_w + (long)idx_sh[rowL] * QD_ + (k0 - 128) + kq);
                pa1 = *(const float4*)(q_w + (long)idx_sh[rowL + 64] * QD_ + (k0 - 128) + kq);
            }
            cp16(bs_base + nb * BS_BUF + bo0, g_rwT + (k0 + bkk0) * 128 + bcc0);
            cp16(bs_base + nb * BS_BUF + bo1, g_rwT + (k0 + bkk1) * 128 + bcc1);
            CP_COMMIT();
        }
#pragma unroll
        for (int kk = 0; kk < 16; kk++) {
            const float* ap = &As[cur][kk][ty * 8];
            float4 a0 = *(const float4*)ap;
            float4 a1 = *(const float4*)(ap + 4);
            ulonglong2 b01 = *(const ulonglong2*)&Bs[cur][kk][tx * 8];
            ulonglong2 b23 = *(const ulonglong2*)(&Bs[cur][kk][tx * 8] + 4);
            ull ad[8] = {dup2(a0.x), dup2(a0.y), dup2(a0.z), dup2(a0.w),
                         dup2(a1.x), dup2(a1.y), dup2(a1.z), dup2(a1.w)};
#pragma unroll
            for (int i = 0; i < 8; i++) {
                fma2(acc[i][0], ad[i], b01.x);
                fma2(acc[i][1], ad[i], b01.y);
                fma2(acc[i][2], ad[i], b23.x);
                fma2(acc[i][3], ad[i], b23.y);
            }
        }
        if (c + 1 < 16) {
            float* a = &As[nb][kq][0];
            a[0*132+rowL]=pa0.x; a[1*132+rowL]=pa0.y; a[2*132+rowL]=pa0.z; a[3*132+rowL]=pa0.w;
            a[0*132+rowL+64]=pa1.x; a[1*132+rowL+64]=pa1.y; a[2*132+rowL+64]=pa1.z; a[3*132+rowL+64]=pa1.w;
            CP_WAIT0();
        }
        __syncthreads();
    }

    float pbv = __ldg(pb);
    float s_bce = 0.f, s_m = 0.f;
#pragma unroll
    for (int i = 0; i < 8; i++) {
        int r = r0 + ty * 8 + i;
        float o[8];
        unpack2(acc[i][0], o[0], o[1]);
        unpack2(acc[i][1], o[2], o[3]);
        unpack2(acc[i][2], o[4], o[5]);
        unpack2(acc[i][3], o[6], o[7]);
        float part = 0.f;
#pragma unroll
        for (int j = 0; j < 8; j++) {
            int vv = tx * 8 + j;
            float hv = tanhf(o[j] + __ldg(rb + vv));
            part = fmaf(hv, __ldg(pw + vv), part);
        }
        part += __shfl_xor_sync(0xFFFFFFFFu, part, 1);
        part += __shfl_xor_sync(0xFFFFFFFFu, part, 2);
        part += __shfl_xor_sync(0xFFFFFFFFu, part, 4);
        part += __shfl_xor_sync(0xFFFFFFFFu, part, 8);
        if (tx == 0) {
            float logit = part + pbv;
            float pred = 1.f / (1.f + __expf(-logit));
            float tgt  = target[r];
            out[1 + r]      = pred;
            out[1 + BS + r] = tgt;
            float spa = log1pf(__expf(-fabsf(logit)));
            float sp_n = fmaxf(-logit, 0.f) + spa;
            float sp_p = fmaxf(logit, 0.f) + spa;
            float msk = (tgt >= 0.f) ? 1.f : 0.f;
            s_bce += (tgt * sp_n + (1.f - tgt) * sp_p) * msk;
            s_m   += msk;
        }
    }

    __shared__ float sb[8], smm[8];
#pragma unroll
    for (int o = 16; o; o >>= 1) {
        s_bce += __shfl_xor_sync(0xFFFFFFFFu, s_bce, o);
        s_m   += __shfl_xor_sync(0xFFFFFFFFu, s_m, o);
    }
    int lane = tid & 31, wid = tid >> 5;
    if (lane == 0) { sb[wid] = s_bce; smm[wid] = s_m; }
    __syncthreads();
    if (tid == 0) {
        float tb = 0.f, tm = 0.f;
#pragma unroll
        for (int i = 0; i < 8; i++) { tb += sb[i]; tm += smm[i]; }
        g_partial[2 * blockIdx.x]     = tb;
        g_partial[2 * blockIdx.x + 1] = tm;
    }
}

__global__ void loss_kernel(float* __restrict__ out) {
    if (threadIdx.x == 0) {
        float tb = 0.f, tm = 0.f;
        for (int i = 0; i < 128; i++) { tb += g_partial[2 * i]; tm += g_partial[2 * i + 1]; }
        out[0] = tb / fmaxf(tm, 1.f);
    }
}

// ============================================================================
extern "C" void kernel_launch(void* const* d_in, const int* in_sizes, int n_in,
                              void* d_out, int out_size) {
    const int*   q_data    = (const int*)d_in[0];
    const int*   qa_data   = (const int*)d_in[1];
    const float* target    = (const float*)d_in[2];
    const float* q_embed   = (const float*)d_in[3];
    const float* qa_embed  = (const float*)d_in[4];
    const float* mem_key   = (const float*)d_in[5];
    const float* mem_val0  = (const float*)d_in[6];
    const float* erase_w   = (const float*)d_in[7];
    const float* erase_b   = (const float*)d_in[8];
    const float* add_w     = (const float*)d_in[9];
    const float* add_b     = (const float*)d_in[10];
    const float* read_w    = (const float*)d_in[11];
    const float* read_b    = (const float*)d_in[12];
    const float* pred_w    = (const float*)d_in[13];
    const float* pred_b    = (const float*)d_in[14];
    float* out = (float*)d_out;

    cudaFuncSetAttribute(scan_kernel, cudaFuncAttributeMaxDynamicSharedMemorySize, 131072);
    cudaFuncSetAttribute(ea_kernel, cudaFuncAttributeMaxDynamicSharedMemorySize, 98304);

    transpose_kernel<<<dim3(128, 4), 256>>>(erase_w, add_w, read_w, mem_key);
    w_kernel        <<<BS / 128, 256>>>(q_data, q_embed);
    ea_kernel       <<<BS / 128, 512, 98304>>>(qa_data, qa_embed, erase_b, add_b);
    scan_kernel     <<<B_ * 4, 512, 131072>>>(mem_val0);
    read_pred_kernel<<<BS / 128, 256>>>(q_data, q_embed, read_b, target, pred_w, pred_b, out);
    loss_kernel     <<<1, 32>>>(out);
}

// round 17
// speedup vs baseline: 1.6195x; 1.1996x over previous
#include <cuda_runtime.h>
#include <cuda_bf16.h>
#include <math.h>

#define B_    64
#define S_    256
#define BS    16384
#define M_    64
#define QD_   128
#define QAD_  256
#define VD_   128
#define FD_   128

typedef unsigned long long ull;

// ---------------- scratch ----------------
__device__ float g_w[BS * M_];
__device__ float g_e[BS * VD_];
__device__ float g_a[BS * VD_];
__device__ float g_reads[BS * VD_];
__device__ float g_partial[2 * 128];
__device__ float g_Bfrag[8 * 32 * 2 * 32 * 4];   // ea weights, tf32 fragment-permuted
__device__ float g_rwBfrag[8 * 16 * 2 * 32 * 4]; // read_w, tf32 fragment-permuted
__device__ float g_keyT[QD_ * M_];               // [128][64]

// ---------------- helpers ----------------
__device__ __forceinline__ ull dup2(float x) {
    ull r; unsigned xi = __float_as_uint(x);
    asm("mov.b64 %0, {%1, %1};" : "=l"(r) : "r"(xi));
    return r;
}
__device__ __forceinline__ ull pack2(float lo, float hi) {
    ull r; unsigned a = __float_as_uint(lo), b = __float_as_uint(hi);
    asm("mov.b64 %0, {%1, %2};" : "=l"(r) : "r"(a), "r"(b));
    return r;
}
__device__ __forceinline__ void unpack2(ull v, float& lo, float& hi) {
    unsigned a, b;
    asm("mov.b64 {%0, %1}, %2;" : "=r"(a), "=r"(b) : "l"(v));
    lo = __uint_as_float(a); hi = __uint_as_float(b);
}
__device__ __forceinline__ void fma2(ull& d, ull a, ull b) {
    asm("fma.rn.f32x2 %0, %1, %2, %0;" : "+l"(d) : "l"(a), "l"(b));
}
__device__ __forceinline__ void cp16(unsigned s, const float* g) {
    asm volatile("cp.async.cg.shared.global [%0], [%1], 16;" :: "r"(s), "l"(g));
}
#define CP_COMMIT() asm volatile("cp.async.commit_group;")
#define CP_WAIT0()  asm volatile("cp.async.wait_group 0;" ::: "memory")

__device__ __forceinline__ unsigned tf32cvt(float f) {
    unsigned u; asm("cvt.rna.tf32.f32 %0, %1;" : "=r"(u) : "f"(f));
    return u;
}
__device__ __forceinline__ void sts32(unsigned addr, unsigned v) {
    asm volatile("st.shared.b32 [%0], %1;" :: "r"(addr), "r"(v));
}
__device__ __forceinline__ void lds128(uint4& d, unsigned addr) {
    asm volatile("ld.shared.v4.b32 {%0,%1,%2,%3}, [%4];"
                 : "=r"(d.x), "=r"(d.y), "=r"(d.z), "=r"(d.w) : "r"(addr));
}
__device__ __forceinline__ void mma_tf32(float* d, const unsigned* a, unsigned b0, unsigned b1) {
    asm volatile("mma.sync.aligned.m16n8k8.row.col.f32.tf32.tf32.f32 "
                 "{%0,%1,%2,%3}, {%4,%5,%6,%7}, {%8,%9}, {%0,%1,%2,%3};"
                 : "+f"(d[0]), "+f"(d[1]), "+f"(d[2]), "+f"(d[3])
                 : "r"(a[0]), "r"(a[1]), "r"(a[2]), "r"(a[3]), "r"(b0), "r"(b1));
}

// ============================================================================
// K0: weight prep. which 0/1: erase/add -> g_Bfrag (NT=32).
//     which 2: read_w -> g_rwBfrag (NT=16).  which 3: mem_key -> g_keyT.
// ============================================================================
__global__ void transpose_kernel(const float* __restrict__ ew,
                                 const float* __restrict__ aw,
                                 const float* __restrict__ rw,
                                 const float* __restrict__ key) {
    int t = blockIdx.x * 256 + threadIdx.x;
    int which = blockIdx.y;
    if (which < 3) {
        int n = t >> 8, k = t & 255;           // n 0..127, k 0..255
        const float* src = which == 0 ? ew : (which == 1 ? aw : rw);
        unsigned uv = tf32cvt(src[n * 256 + k]);
        int kb = k >> 5, ks = (k >> 3) & 3, kp = ks >> 1, par = ks & 1;
        int k8 = k & 7, tt = k8 & 3, j = k8 >> 2;
        int g = n & 7;
        int lanef = g * 4 + tt, reg = par * 2 + j;
        if (which < 2) {
            int ntg = which * 16 + (n >> 3);
            int off = (((kb * 32 + ntg) * 2 + kp) * 32 + lanef) * 4 + reg;
            ((unsigned*)g_Bfrag)[off] = uv;
        } else {
            int ntg = n >> 3;
            int off = (((kb * 16 + ntg) * 2 + kp) * 32 + lanef) * 4 + reg;
            ((unsigned*)g_rwBfrag)[off] = uv;
        }
    } else {
        if (t < QD_ * M_) {
            int k = t >> 6, n = t & 63;
            g_keyT[k * 64 + n] = key[n * 128 + k];
        }
    }
}

// ============================================================================
// K1: w = softmax(q_emb @ mem_key^T)   (unchanged)
// ============================================================================
__global__ __launch_bounds__(256, 2) void w_kernel(const int* __restrict__ q_data,
                                                   const float* __restrict__ q_w) {
    __shared__ union {
        struct {
            __align__(16) float As[2][16][132];
            __align__(16) float Bs[2][16][68];
        } g;
        float logits[128][65];
    } sm;
    __shared__ int idx_sh[128];

    int tid = threadIdx.x;
    int r0  = blockIdx.x * 128;
    if (tid < 128) idx_sh[tid] = q_data[r0 + tid];
    __syncthreads();

    int tx = tid & 15, ty = tid >> 4;
    int rowL = tid >> 2;
    int kq   = (tid & 3) * 4;

    int bkk = tid >> 4, bcc = (tid & 15) * 4;
    unsigned bs_base = (unsigned)__cvta_generic_to_shared(&sm.g.Bs[0][0][0]);
    unsigned bs_off  = (unsigned)((bkk * 68 + bcc) * 4);
    const unsigned BS_BUF = 16 * 68 * 4;

    ull acc[8][2];
#pragma unroll
    for (int i = 0; i < 8; i++) { acc[i][0] = 0ull; acc[i][1] = 0ull; }

    float4 pa0, pa1;
    pa0 = *(const float4*)(q_w + (long)idx_sh[rowL] * QD_ + kq);
    pa1 = *(const float4*)(q_w + (long)idx_sh[rowL + 64] * QD_ + kq);
    cp16(bs_base + bs_off, g_keyT + bkk * 64 + bcc);
    CP_COMMIT();
    {
        float* a = &sm.g.As[0][kq][0];
        a[0*132+rowL]=pa0.x; a[1*132+rowL]=pa0.y; a[2*132+rowL]=pa0.z; a[3*132+rowL]=pa0.w;
        a[0*132+rowL+64]=pa1.x; a[1*132+rowL+64]=pa1.y; a[2*132+rowL+64]=pa1.z; a[3*132+rowL+64]=pa1.w;
    }
    CP_WAIT0();
    __syncthreads();

    for (int c = 0; c < 8; c++) {
        int cur = c & 1, nb = cur ^ 1;
        if (c + 1 < 8) {
            int k0 = (c + 1) * 16;
            pa0 = *(const float4*)(q_w + (long)idx_sh[rowL] * QD_ + k0 + kq);
            pa1 = *(const float4*)(q_w + (long)idx_sh[rowL + 64] * QD_ + k0 + kq);
            cp16(bs_base + nb * BS_BUF + bs_off, g_keyT + (k0 + bkk) * 64 + bcc);
            CP_COMMIT();
        }
#pragma unroll
        for (int kk = 0; kk < 16; kk++) {
            const float* ap = &sm.g.As[cur][kk][ty * 8];
            float4 a0 = *(const float4*)ap;
            float4 a1 = *(const float4*)(ap + 4);
            ulonglong2 bv = *(const ulonglong2*)&sm.g.Bs[cur][kk][tx * 4];
            ull ad[8] = {dup2(a0.x), dup2(a0.y), dup2(a0.z), dup2(a0.w),
                         dup2(a1.x), dup2(a1.y), dup2(a1.z), dup2(a1.w)};
#pragma unroll
            for (int i = 0; i < 8; i++) {
                fma2(acc[i][0], ad[i], bv.x);
                fma2(acc[i][1], ad[i], bv.y);
            }
        }
        if (c + 1 < 8) {
            float* a = &sm.g.As[nb][kq][0];
            a[0*132+rowL]=pa0.x; a[1*132+rowL]=pa0.y; a[2*132+rowL]=pa0.z; a[3*132+rowL]=pa0.w;
            a[0*132+rowL+64]=pa1.x; a[1*132+rowL+64]=pa1.y; a[2*132+rowL+64]=pa1.z; a[3*132+rowL+64]=pa1.w;
            CP_WAIT0();
        }
        __syncthreads();
    }

#pragma unroll
    for (int i = 0; i < 8; i++) {
        float v0, v1, v2, v3;
        unpack2(acc[i][0], v0, v1);
        unpack2(acc[i][1], v2, v3);
        float* lr = &sm.logits[ty * 8 + i][tx * 4];
        lr[0] = v0; lr[1] = v1; lr[2] = v2; lr[3] = v3;
    }
    __syncthreads();

    int wid = tid >> 5, lane = tid & 31;
    for (int rr = wid; rr < 128; rr += 8) {
        float v0 = sm.logits[rr][lane], v1 = sm.logits[rr][lane + 32];
        float mx = fmaxf(v0, v1);
#pragma unroll
        for (int o = 16; o; o >>= 1) mx = fmaxf(mx, __shfl_xor_sync(0xFFFFFFFFu, mx, o));
        float e0 = __expf(v0 - mx), e1 = __expf(v1 - mx);
        float s = e0 + e1;
#pragma unroll
        for (int o = 16; o; o >>= 1) s += __shfl_xor_sync(0xFFFFFFFFu, s, o);
        float inv = 1.f / s;
        g_w[(r0 + rr) * M_ + lane]      = e0 * inv;
        g_w[(r0 + rr) * M_ + 32 + lane] = e1 * inv;
    }
}

// ============================================================================
// K2: e/a via tf32 mma (unchanged from R16)
// ============================================================================
__global__ __launch_bounds__(512, 1) void ea_kernel(const int* __restrict__ qa_data,
                                                    const float* __restrict__ qa_w,
                                                    const float* __restrict__ eb,
                                                    const float* __restrict__ ab) {
    extern __shared__ float eas[];
    float* Af = eas;                 // [2][4096]
    float* Bf = eas + 8192;          // [2][8192]
    __shared__ int idx_sh[128];

    int tid = threadIdx.x;
    int r0  = blockIdx.x * 128;
    if (tid < 128) idx_sh[tid] = qa_data[r0 + tid];
    __syncthreads();

    int lane = tid & 31, wid = tid >> 5;
    int warp_m = wid & 3, warp_n = wid >> 2;

    unsigned sA = (unsigned)__cvta_generic_to_shared(Af);
    unsigned sB = (unsigned)__cvta_generic_to_shared(Bf);
    const unsigned A_BUF = 4096 * 4, B_BUF = 8192 * 4;

    int q0 = tid, q1 = tid + 512;
    int row0 = q0 >> 3, kq0 = q0 & 7;
    int row1 = q1 >> 3, kq1 = q1 & 7;
    const float* arow0 = qa_w + (long)idx_sh[row0] * QAD_;
    const float* arow1 = qa_w + (long)idx_sh[row1] * QAD_;

    unsigned offA[2][4];
#pragma unroll
    for (int qq = 0; qq < 2; qq++) {
        int row = qq ? row1 : row0, kqv = qq ? kq1 : kq0;
        int mt = row >> 4, r16 = row & 15, g = r16 & 7, im = r16 >> 3;
#pragma unroll
        for (int cc = 0; cc < 4; cc++) {
            int cl = kqv * 4 + cc;
            int ks = cl >> 3, k8 = cl & 7, tt = k8 & 3, j = k8 >> 2;
            int lanef = g * 4 + tt, reg = im + 2 * j;
            offA[qq][cc] = (unsigned)((((mt * 4 + ks) * 32 + lanef) * 4 + reg) * 4);
        }
    }

    float acc[2][8][4];
#pragma unroll
    for (int i = 0; i < 2; i++)
#pragma unroll
        for (int j = 0; j < 8; j++)
#pragma unroll
            for (int k = 0; k < 4; k++) acc[i][j][k] = 0.f;

    float4 av0 = *(const float4*)(arow0 + kq0 * 4);
    float4 av1 = *(const float4*)(arow1 + kq1 * 4);
#pragma unroll
    for (int ci = 0; ci < 4; ci++) {
        int c = tid + 512 * ci;
        cp16(sB + c * 16, g_Bfrag + c * 4);
    }
    CP_COMMIT();
    sts32(sA + offA[0][0], tf32cvt(av0.x)); sts32(sA + offA[0][1], tf32cvt(av0.y));
    sts32(sA + offA[0][2], tf32cvt(av0.z)); sts32(sA + offA[0][3], tf32cvt(av0.w));
    sts32(sA + offA[1][0], tf32cvt(av1.x)); sts32(sA + offA[1][1], tf32cvt(av1.y));
    sts32(sA + offA[1][2], tf32cvt(av1.z)); sts32(sA + offA[1][3], tf32cvt(av1.w));
    CP_WAIT0();
    __syncthreads();

    for (int kb = 0; kb < 8; kb++) {
        int cur = kb & 1, nb = cur ^ 1;
        if (kb + 1 < 8) {
            av0 = *(const float4*)(arow0 + (kb + 1) * 32 + kq0 * 4);
            av1 = *(const float4*)(arow1 + (kb + 1) * 32 + kq1 * 4);
#pragma unroll
            for (int ci = 0; ci < 4; ci++) {
                int c = tid + 512 * ci;
                cp16(sB + nb * B_BUF + c * 16, g_Bfrag + (kb + 1) * 8192 + c * 4);
            }
            CP_COMMIT();
        }
        unsigned aB = sA + cur * A_BUF;
        unsigned bB = sB + cur * B_BUF;
#pragma unroll
        for (int kp = 0; kp < 2; kp++) {
            uint4 afr[2][2];
#pragma unroll
            for (int mtl = 0; mtl < 2; mtl++)
#pragma unroll
                for (int par = 0; par < 2; par++) {
                    int mt = warp_m * 2 + mtl, ks = kp * 2 + par;
                    lds128(afr[mtl][par], aB + (unsigned)(((mt * 4 + ks) * 32 + lane) * 16));
                }
#pragma unroll
            for (int ntl = 0; ntl < 8; ntl++) {
                int nt = warp_n * 8 + ntl;
                uint4 bfr;
                lds128(bfr, bB + (unsigned)(((nt * 2 + kp) * 32 + lane) * 16));
#pragma unroll
                for (int mtl = 0; mtl < 2; mtl++) {
                    mma_tf32(acc[mtl][ntl], (const unsigned*)&afr[mtl][0], bfr.x, bfr.y);
                    mma_tf32(acc[mtl][ntl], (const unsigned*)&afr[mtl][1], bfr.z, bfr.w);
                }
            }
        }
        if (kb + 1 < 8) {
            unsigned aN = sA + nb * A_BUF;
            sts32(aN + offA[0][0], tf32cvt(av0.x)); sts32(aN + offA[0][1], tf32cvt(av0.y));
            sts32(aN + offA[0][2], tf32cvt(av0.z)); sts32(aN + offA[0][3], tf32cvt(av0.w));
            sts32(aN + offA[1][0], tf32cvt(av1.x)); sts32(aN + offA[1][1], tf32cvt(av1.y));
            sts32(aN + offA[1][2], tf32cvt(av1.z)); sts32(aN + offA[1][3], tf32cvt(av1.w));
            CP_WAIT0();
        }
        __syncthreads();
    }

    int matrix = warp_n >> 1;
    int colb = (warp_n & 1) * 64;
    float* dst = matrix ? g_a : g_e;
    const float* bias = matrix ? ab : eb;
    int g = lane >> 2, t2 = (lane & 3) * 2;
#pragma unroll
    for (int ntl = 0; ntl < 8; ntl++) {
        int col = colb + ntl * 8 + t2;
        float b0v = __ldg(bias + col), b1v = __ldg(bias + col + 1);
#pragma unroll
        for (int mtl = 0; mtl < 2; mtl++) {
            int rowb = r0 + warp_m * 32 + mtl * 16 + g;
            float x0 = acc[mtl][ntl][0] + b0v, x1 = acc[mtl][ntl][1] + b1v;
            float x2 = acc[mtl][ntl][2] + b0v, x3 = acc[mtl][ntl][3] + b1v;
            float y0, y1, y2, y3;
            if (matrix) {
                y0 = tanhf(x0); y1 = tanhf(x1); y2 = tanhf(x2); y3 = tanhf(x3);
            } else {
                y0 = 1.f / (1.f + __expf(-x0)); y1 = 1.f / (1.f + __expf(-x1));
                y2 = 1.f / (1.f + __expf(-x2)); y3 = 1.f / (1.f + __expf(-x3));
            }
            *(float2*)(dst + (long)rowb * VD_ + col) = make_float2(y0, y1);
            *(float2*)(dst + (long)(rowb + 8) * VD_ + col) = make_float2(y2, y3);
        }
    }
}

// ============================================================================
// K3: sequential memory scan (R13 config, unchanged)
// ============================================================================
__global__ __launch_bounds__(512) void scan_kernel(const float* __restrict__ mem_value0) {
    extern __shared__ float smd[];
    float* w_all  = smd;
    float* ea_all = smd + S_ * 64;

    int bb = blockIdx.x >> 2, vh = blockIdx.x & 3;
    int tid = threadIdx.x;
    int rbase = bb * S_;

    const float4* wsrc = (const float4*)(g_w + (long)rbase * M_);
    float4* wdst = (float4*)w_all;
    for (int i = tid; i < S_ * M_ / 4; i += 512) wdst[i] = wsrc[i];
    for (int f = tid; f < S_ * 8; f += 512) {
        int t = f >> 3, c = (f & 7) * 4;
        float4 e4 = *(const float4*)(g_e + (long)(rbase + t) * VD_ + vh * 32 + c);
        float4 a4 = *(const float4*)(g_a + (long)(rbase + t) * VD_ + vh * 32 + c);
        float* base = &ea_all[(t >> 1) * 128 + (t & 1) * 2];
        *(float2*)&base[(c + 0) * 4] = make_float2(e4.x, a4.x);
        *(float2*)&base[(c + 1) * 4] = make_float2(e4.y, a4.y);
        *(float2*)&base[(c + 2) * 4] = make_float2(e4.z, a4.z);
        *(float2*)&base[(c + 3) * 4] = make_float2(e4.w, a4.w);
    }

    int lane = tid & 31, wid = tid >> 5;
    int mh = lane & 15, vl = lane >> 4;
    int vloc = wid * 2 + vl;
    int v = vh * 32 + vloc;
    int mb = mh * 4;

    ull mm[2];
#pragma unroll
    for (int i = 0; i < 2; i++) {
        int m0 = mb + 2 * i;
        mm[i] = pack2(mem_value0[m0 * VD_ + v], mem_value0[(m0 + 1) * VD_ + v]);
    }
    bool b8 = (mh & 8) != 0, b4 = (mh & 4) != 0, b2 = (mh & 2) != 0, b1 = (mh & 1) != 0;
    __syncthreads();

    for (int t0 = 0; t0 < S_; t0 += 16) {
        float p[16];
#pragma unroll
        for (int j = 0; j < 8; j++) {
            float4 eab = *(const float4*)&ea_all[((t0 >> 1) + j) * 128 + vloc * 4];
#pragma unroll
            for (int s = 0; s < 2; s++) {
                int u = 2 * j + s;
                float ec = s ? eab.z : eab.x;
                float ac = s ? eab.w : eab.y;
                ull ne2 = dup2(-ec);
                ull a2v = dup2(ac);
                ulonglong2 wA = *(const ulonglong2*)&w_all[(t0 + u) * 64 + mb];
                ull rd2 = 0ull;
#pragma unroll
                for (int i = 0; i < 2; i++) {
                    ull w2 = (i == 0) ? wA.x : wA.y;
                    ull tt = a2v; fma2(tt, ne2, mm[i]);
                    fma2(rd2, w2, mm[i]);
                    fma2(mm[i], w2, tt);
                }
                float rl, rh; unpack2(rd2, rl, rh);
                p[u] = rl + rh;
            }
        }

        float q8[8];
#pragma unroll
        for (int x = 0; x < 8; x++) {
            float send = b8 ? p[x] : p[x + 8];
            float recv = __shfl_xor_sync(0xFFFFFFFFu, send, 8);
            q8[x] = (b8 ? p[x + 8] : p[x]) + recv;
        }
        float q4[4];
#pragma unroll
        for (int x = 0; x < 4; x++) {
            float send = b4 ? q8[x] : q8[x + 4];
            float recv = __shfl_xor_sync(0xFFFFFFFFu, send, 4);
            q4[x] = (b4 ? q8[x + 4] : q8[x]) + recv;
        }
        float q2[2];
#pragma unroll
        for (int x = 0; x < 2; x++) {
            float send = b2 ? q4[x] : q4[x + 2];
            float recv = __shfl_xor_sync(0xFFFFFFFFu, send, 2);
            q2[x] = (b2 ? q4[x + 2] : q4[x]) + recv;
        }
        {
            float send = b1 ? q2[0] : q2[1];
            float recv = __shfl_xor_sync(0xFFFFFFFFu, send, 1);
            float rd = (b1 ? q2[1] : q2[0]) + recv;
            g_reads[(long)(rbase + t0 + mh) * VD_ + v] = rd;
        }
    }
}

// ============================================================================
// K4: read+pred via tf32 mma.  512 threads = 16 warps (4 m x 4 n over N=128).
//   A = [reads | q_emb], K=256.  Epilogue: tanh -> pred dot -> BCE, h never stored.
// ============================================================================
__global__ __launch_bounds__(512, 1) void read_pred_kernel(const int* __restrict__ q_data,
                                                           const float* __restrict__ q_w,
                                                           const float* __restrict__ rb,
                                                           const float* __restrict__ target,
                                                           const float* __restrict__ pw,
                                                           const float* __restrict__ pb,
                                                           float* __restrict__ out) {
    extern __shared__ float rps[];
    float* Af = rps;                 // [2][4096]
    float* Bf = rps + 8192;          // [2][4096]
    __shared__ int idx_sh[128];
    __shared__ float sred[128][5];
    __shared__ float sbce[4], smsk[4];

    int tid = threadIdx.x;
    int r0  = blockIdx.x * 128;
    if (tid < 128) idx_sh[tid] = q_data[r0 + tid];
    __syncthreads();

    int lane = tid & 31, wid = tid >> 5;
    int warp_m = wid & 3, warp_n = wid >> 2;

    unsigned sA = (unsigned)__cvta_generic_to_shared(Af);
    unsigned sB = (unsigned)__cvta_generic_to_shared(Bf);
    const unsigned A_BUF = 4096 * 4, B_BUF = 4096 * 4;

    int q0 = tid, q1 = tid + 512;
    int row0 = q0 >> 3, kq0 = q0 & 7;
    int row1 = q1 >> 3, kq1 = q1 & 7;

    unsigned offA[2][4];
#pragma unroll
    for (int qq = 0; qq < 2; qq++) {
        int row = qq ? row1 : row0, kqv = qq ? kq1 : kq0;
        int mt = row >> 4, r16 = row & 15, g = r16 & 7, im = r16 >> 3;
#pragma unroll
        for (int cc = 0; cc < 4; cc++) {
            int cl = kqv * 4 + cc;
            int ks = cl >> 3, k8 = cl & 7, tt = k8 & 3, j = k8 >> 2;
            int lanef = g * 4 + tt, reg = im + 2 * j;
            offA[qq][cc] = (unsigned)((((mt * 4 + ks) * 32 + lanef) * 4 + reg) * 4);
        }
    }

    // A source: kb<4 -> reads, kb>=4 -> q_emb
#define ALOAD(av, rowv, kqv, kbv)                                              \
    if ((kbv) < 4) (av) = *(const float4*)(g_reads + (long)(r0 + (rowv)) * VD_ + (kbv) * 32 + (kqv) * 4); \
    else           (av) = *(const float4*)(q_w + (long)idx_sh[rowv] * QD_ + ((kbv) - 4) * 32 + (kqv) * 4);

    float acc[2][4][4];
#pragma unroll
    for (int i = 0; i < 2; i++)
#pragma unroll
        for (int j = 0; j < 4; j++)
#pragma unroll
            for (int k = 0; k < 4; k++) acc[i][j][k] = 0.f;

    float4 av0, av1;
    ALOAD(av0, row0, kq0, 0)
    ALOAD(av1, row1, kq1, 0)
#pragma unroll
    for (int ci = 0; ci < 2; ci++) {
        int c = tid + 512 * ci;
        cp16(sB + c * 16, g_rwBfrag + c * 4);
    }
    CP_COMMIT();
    sts32(sA + offA[0][0], tf32cvt(av0.x)); sts32(sA + offA[0][1], tf32cvt(av0.y));
    sts32(sA + offA[0][2], tf32cvt(av0.z)); sts32(sA + offA[0][3], tf32cvt(av0.w));
    sts32(sA + offA[1][0], tf32cvt(av1.x)); sts32(sA + offA[1][1], tf32cvt(av1.y));
    sts32(sA + offA[1][2], tf32cvt(av1.z)); sts32(sA + offA[1][3], tf32cvt(av1.w));
    CP_WAIT0();
    __syncthreads();

    for (int kb = 0; kb < 8; kb++) {
        int cur = kb & 1, nb = cur ^ 1;
        if (kb + 1 < 8) {
            int kbn = kb + 1;
            ALOAD(av0, row0, kq0, kbn)
            ALOAD(av1, row1, kq1, kbn)
#pragma unroll
            for (int ci = 0; ci < 2; ci++) {
                int c = tid + 512 * ci;
                cp16(sB + nb * B_BUF + c * 16, g_rwBfrag + kbn * 4096 + c * 4);
            }
            CP_COMMIT();
        }
        unsigned aB = sA + cur * A_BUF;
        unsigned bB = sB + cur * B_BUF;
#pragma unroll
        for (int kp = 0; kp < 2; kp++) {
            uint4 afr[2][2];
#pragma unroll
            for (int mtl = 0; mtl < 2; mtl++)
#pragma unroll
                for (int par = 0; par < 2; par++) {
                    int mt = warp_m * 2 + mtl, ks = kp * 2 + par;
                    lds128(afr[mtl][par], aB + (unsigned)(((mt * 4 + ks) * 32 + lane) * 16));
                }
#pragma unroll
            for (int ntl = 0; ntl < 4; ntl++) {
                int nt = warp_n * 4 + ntl;
                uint4 bfr;
                lds128(bfr, bB + (unsigned)(((nt * 2 + kp) * 32 + lane) * 16));
#pragma unroll
                for (int mtl = 0; mtl < 2; mtl++) {
                    mma_tf32(acc[mtl][ntl], (const unsigned*)&afr[mtl][0], bfr.x, bfr.y);
                    mma_tf32(acc[mtl][ntl], (const unsigned*)&afr[mtl][1], bfr.z, bfr.w);
                }
            }
        }
        if (kb + 1 < 8) {
            unsigned aN = sA + nb * A_BUF;
            sts32(aN + offA[0][0], tf32cvt(av0.x)); sts32(aN + offA[0][1], tf32cvt(av0.y));
            sts32(aN + offA[0][2], tf32cvt(av0.z)); sts32(aN + offA[0][3], tf32cvt(av0.w));
            sts32(aN + offA[1][0], tf32cvt(av1.x)); sts32(aN + offA[1][1], tf32cvt(av1.y));
            sts32(aN + offA[1][2], tf32cvt(av1.z)); sts32(aN + offA[1][3], tf32cvt(av1.w));
            CP_WAIT0();
        }
        __syncthreads();
    }
#undef ALOAD

    // epilogue: tanh + pred-dot per fragment; quad reduce; cross-warp_n reduce
    int g = lane >> 2, t2q = lane & 3;
    float prt[2][2] = {{0.f, 0.f}, {0.f, 0.f}};
#pragma unroll
    for (int ntl = 0; ntl < 4; ntl++) {
        int col = warp_n * 32 + ntl * 8 + t2q * 2;
        float rb0 = __ldg(rb + col), rb1 = __ldg(rb + col + 1);
        float pw0 = __ldg(pw + col), pw1 = __ldg(pw + col + 1);
#pragma unroll
        for (int mtl = 0; mtl < 2; mtl++) {
            prt[mtl][0] += tanhf(acc[mtl][ntl][0] + rb0) * pw0
                         + tanhf(acc[mtl][ntl][1] + rb1) * pw1;
            prt[mtl][1] += tanhf(acc[mtl][ntl][2] + rb0) * pw0
                         + tanhf(acc[mtl][ntl][3] + rb1) * pw1;
        }
    }
#pragma unroll
    for (int mtl = 0; mtl < 2; mtl++)
#pragma unroll
        for (int h = 0; h < 2; h++) {
            prt[mtl][h] += __shfl_xor_sync(0xFFFFFFFFu, prt[mtl][h], 1);
            prt[mtl][h] += __shfl_xor_sync(0xFFFFFFFFu, prt[mtl][h], 2);
        }
    if (t2q == 0) {
#pragma unroll
        for (int mtl = 0; mtl < 2; mtl++)
#pragma unroll
            for (int h = 0; h < 2; h++) {
                int rowL = warp_m * 32 + mtl * 16 + h * 8 + g;
                sred[rowL][warp_n] = prt[mtl][h];
            }
    }
    __syncthreads();

    float s_bce = 0.f, s_m = 0.f;
    if (tid < 128) {
        int r = r0 + tid;
        float logit = sred[tid][0] + sred[tid][1] + sred[tid][2] + sred[tid][3] + __ldg(pb);
        float pred = 1.f / (1.f + __expf(-logit));
        float tgt  = target[r];
        out[1 + r]      = pred;
        out[1 + BS + r] = tgt;
        float spa = log1pf(__expf(-fabsf(logit)));
        float sp_n = fmaxf(-logit, 0.f) + spa;
        float sp_p = fmaxf(logit, 0.f) + spa;
        float msk = (tgt >= 0.f) ? 1.f : 0.f;
        s_bce = (tgt * sp_n + (1.f - tgt) * sp_p) * msk;
        s_m   = msk;
    }
#pragma unroll
    for (int o = 16; o; o >>= 1) {
        s_bce += __shfl_xor_sync(0xFFFFFFFFu, s_bce, o);
        s_m   += __shfl_xor_sync(0xFFFFFFFFu, s_m, o);
    }
    if (tid < 128 && lane == 0) { sbce[wid] = s_bce; smsk[wid] = s_m; }
    __syncthreads();
    if (tid == 0) {
        g_partial[2 * blockIdx.x]     = sbce[0] + sbce[1] + sbce[2] + sbce[3];
        g_partial[2 * blockIdx.x + 1] = smsk[0] + smsk[1] + smsk[2] + smsk[3];
    }
}

__global__ void loss_kernel(float* __restrict__ out) {
    if (threadIdx.x == 0) {
        float tb = 0.f, tm = 0.f;
        for (int i = 0; i < 128; i++) { tb += g_partial[2 * i]; tm += g_partial[2 * i + 1]; }
        out[0] = tb / fmaxf(tm, 1.f);
    }
}

// ============================================================================
extern "C" void kernel_launch(void* const* d_in, const int* in_sizes, int n_in,
                              void* d_out, int out_size) {
    const int*   q_data    = (const int*)d_in[0];
    const int*   qa_data   = (const int*)d_in[1];
    const float* target    = (const float*)d_in[2];
    const float* q_embed   = (const float*)d_in[3];
    const float* qa_embed  = (const float*)d_in[4];
    const float* mem_key   = (const float*)d_in[5];
    const float* mem_val0  = (const float*)d_in[6];
    const float* erase_w   = (const float*)d_in[7];
    const float* erase_b   = (const float*)d_in[8];
    const float* add_w     = (const float*)d_in[9];
    const float* add_b     = (const float*)d_in[10];
    const float* read_w    = (const float*)d_in[11];
    const float* read_b    = (const float*)d_in[12];
    const float* pred_w    = (const float*)d_in[13];
    const float* pred_b    = (const float*)d_in[14];
    float* out = (float*)d_out;

    cudaFuncSetAttribute(scan_kernel, cudaFuncAttributeMaxDynamicSharedMemorySize, 131072);
    cudaFuncSetAttribute(ea_kernel, cudaFuncAttributeMaxDynamicSharedMemorySize, 98304);
    cudaFuncSetAttribute(read_pred_kernel, cudaFuncAttributeMaxDynamicSharedMemorySize, 65536);

    transpose_kernel<<<dim3(128, 4), 256>>>(erase_w, add_w, read_w, mem_key);
    w_kernel        <<<BS / 128, 256>>>(q_data, q_embed);
    ea_kernel       <<<BS / 128, 512, 98304>>>(qa_data, qa_embed, erase_b, add_b);
    scan_kernel     <<<B_ * 4, 512, 131072>>>(mem_val0);
    read_pred_kernel<<<BS / 128, 512, 65536>>>(q_data, q_embed, read_b, target, pred_w, pred_b, out);
    loss_kernel     <<<1, 32>>>(out);
}